// round 1
// baseline (speedup 1.0000x reference)
#include <cuda_runtime.h>
#include <cstdint>

// Problem constants
#define BATCH 4
#define SEQ   2048
#define DMODEL 1024
#define NHEAD 16
#define HDIM  64
#define MROWS (BATCH * SEQ)          // 8192
#define SOFTMAX_SCALE 0.125f         // 1/sqrt(64)

// ---------------------------------------------------------------------------
// Scratch (static device globals -- no allocation allowed)
// ---------------------------------------------------------------------------
__device__ float g_Q[MROWS * DMODEL];
__device__ float g_K[MROWS * DMODEL];
__device__ float g_V[MROWS * DMODEL];
__device__ float g_C[MROWS * DMODEL];

// ---------------------------------------------------------------------------
// SGEMM: C = A[M,K] @ B[K,N] (+ bias).  128x128 tile, 8x8 per thread, BK=8.
// M, N, K all multiples of 128 here; no bounds checks.
// ---------------------------------------------------------------------------
#define BM 128
#define BN 128
#define BK 8

__global__ __launch_bounds__(256)
void sgemm_kernel(const float* __restrict__ A, const float* __restrict__ B,
                  float* __restrict__ C, const float* __restrict__ bias,
                  int M, int N, int K)
{
    __shared__ float As[BK][BM];
    __shared__ float Bs[BK][BN];

    const int tid = threadIdx.x;
    const int bm = blockIdx.y * BM;
    const int bn = blockIdx.x * BN;
    const int tx = tid & 15;         // 0..15
    const int ty = tid >> 4;         // 0..15

    float acc[8][8];
    #pragma unroll
    for (int i = 0; i < 8; ++i)
        #pragma unroll
        for (int j = 0; j < 8; ++j) acc[i][j] = 0.f;

    // cooperative-load indices
    const int arow = tid >> 1;            // 0..127
    const int acol = (tid & 1) * 4;       // 0 or 4
    const int brow = tid >> 5;            // 0..7
    const int bcol = (tid & 31) * 4;      // 0..124

    const float* Aptr = A + (size_t)(bm + arow) * K + acol;
    const float* Bptr = B + (size_t)brow * N + bn + bcol;

    for (int k0 = 0; k0 < K; k0 += BK) {
        float4 a4 = *(const float4*)(Aptr + k0);
        float4 b4 = *(const float4*)(Bptr + (size_t)k0 * N);
        As[acol + 0][arow] = a4.x;
        As[acol + 1][arow] = a4.y;
        As[acol + 2][arow] = a4.z;
        As[acol + 3][arow] = a4.w;
        *(float4*)&Bs[brow][bcol] = b4;
        __syncthreads();

        #pragma unroll
        for (int kk = 0; kk < BK; ++kk) {
            float a[8], b[8];
            #pragma unroll
            for (int i = 0; i < 8; ++i) a[i] = As[kk][ty * 8 + i];
            #pragma unroll
            for (int j = 0; j < 8; ++j) b[j] = Bs[kk][tx * 8 + j];
            #pragma unroll
            for (int i = 0; i < 8; ++i)
                #pragma unroll
                for (int j = 0; j < 8; ++j)
                    acc[i][j] += a[i] * b[j];
        }
        __syncthreads();
    }

    #pragma unroll
    for (int i = 0; i < 8; ++i) {
        const int row = bm + ty * 8 + i;
        #pragma unroll
        for (int j = 0; j < 8; j += 4) {
            const int col = bn + tx * 8 + j;
            float4 v;
            v.x = acc[i][j + 0];
            v.y = acc[i][j + 1];
            v.z = acc[i][j + 2];
            v.w = acc[i][j + 3];
            if (bias) {
                v.x += bias[col + 0];
                v.y += bias[col + 1];
                v.z += bias[col + 2];
                v.w += bias[col + 3];
            }
            *(float4*)&C[(size_t)row * N + col] = v;
        }
    }
}

// ---------------------------------------------------------------------------
// Flash attention (causal), fp32.
// grid: (SEQ/128, BATCH*NHEAD); block: 128 threads, 1 q-row per thread.
// Online softmax over K-tiles of 64, processed in subtiles of 16 to bound
// register pressure (q[64] + acc[64] + s[16]).
// ---------------------------------------------------------------------------
__global__ __launch_bounds__(128)
void attn_kernel()
{
    __shared__ float Ks[64][64];
    __shared__ float Vs[64][64];

    const int qt = blockIdx.x;
    const int bh = blockIdx.y;
    const int b  = bh / NHEAD;
    const int h  = bh % NHEAD;
    const int q0 = qt * 128;
    const int r  = threadIdx.x;
    const int qg = q0 + r;

    const size_t head_off = (size_t)h * HDIM;
    const float* Qrow = g_Q + ((size_t)(b * SEQ + qg)) * DMODEL + head_off;

    float q[HDIM];
    #pragma unroll
    for (int d = 0; d < HDIM; d += 4) {
        float4 t = *(const float4*)(Qrow + d);
        q[d] = t.x; q[d + 1] = t.y; q[d + 2] = t.z; q[d + 3] = t.w;
    }

    float acc[HDIM];
    #pragma unroll
    for (int d = 0; d < HDIM; ++d) acc[d] = 0.f;
    float m = -1e30f;
    float l = 0.f;

    const int ntiles = q0 / 64 + 2;   // covers all k <= q0+127

    for (int jt = 0; jt < ntiles; ++jt) {
        const int j0 = jt * 64;
        const float* Kg = g_K + ((size_t)(b * SEQ + j0)) * DMODEL + head_off;
        const float* Vg = g_V + ((size_t)(b * SEQ + j0)) * DMODEL + head_off;

        __syncthreads();   // protect previous tile's reads
        #pragma unroll
        for (int i = 0; i < 8; ++i) {
            const int idx = r + 128 * i;      // float4 index, 0..1023
            const int row = idx >> 4;         // 0..63
            const int c4  = (idx & 15) * 4;   // 0..60
            *(float4*)&Ks[row][c4] = *(const float4*)(Kg + (size_t)row * DMODEL + c4);
            *(float4*)&Vs[row][c4] = *(const float4*)(Vg + (size_t)row * DMODEL + c4);
        }
        __syncthreads();

        #pragma unroll
        for (int sub = 0; sub < 4; ++sub) {
            float s[16];
            #pragma unroll
            for (int jj = 0; jj < 16; ++jj) {
                const int j = sub * 16 + jj;
                float sv = 0.f;
                #pragma unroll
                for (int d = 0; d < HDIM; ++d)
                    sv += q[d] * Ks[j][d];
                const int kg = j0 + j;
                s[jj] = (kg <= qg) ? sv * SOFTMAX_SCALE : -1e30f;
            }
            float smax = s[0];
            #pragma unroll
            for (int jj = 1; jj < 16; ++jj) smax = fmaxf(smax, s[jj]);
            const float mnew = fmaxf(m, smax);
            const float corr = __expf(m - mnew);
            l *= corr;
            #pragma unroll
            for (int d = 0; d < HDIM; ++d) acc[d] *= corr;
            #pragma unroll
            for (int jj = 0; jj < 16; ++jj) {
                const float p = __expf(s[jj] - mnew);
                l += p;
                const int j = sub * 16 + jj;
                #pragma unroll
                for (int d = 0; d < HDIM; ++d)
                    acc[d] += p * Vs[j][d];
            }
            m = mnew;
        }
    }

    const float inv = 1.f / l;
    float* Crow = g_C + ((size_t)(b * SEQ + qg)) * DMODEL + head_off;
    #pragma unroll
    for (int d = 0; d < HDIM; d += 4) {
        float4 t;
        t.x = acc[d] * inv;
        t.y = acc[d + 1] * inv;
        t.z = acc[d + 2] * inv;
        t.w = acc[d + 3] * inv;
        *(float4*)(Crow + d) = t;
    }
}

// ---------------------------------------------------------------------------
// Launch
// ---------------------------------------------------------------------------
extern "C" void kernel_launch(void* const* d_in, const int* in_sizes, int n_in,
                              void* d_out, int out_size)
{
    const float* x  = (const float*)d_in[0];
    const float* Wq = (const float*)d_in[1];
    const float* Wk = (const float*)d_in[2];
    const float* Wv = (const float*)d_in[3];
    const float* Wo = (const float*)d_in[4];
    const float* bo = (const float*)d_in[5];
    float* out = (float*)d_out;

    float *Qp, *Kp, *Vp, *Cp;
    cudaGetSymbolAddress((void**)&Qp, g_Q);
    cudaGetSymbolAddress((void**)&Kp, g_K);
    cudaGetSymbolAddress((void**)&Vp, g_V);
    cudaGetSymbolAddress((void**)&Cp, g_C);

    dim3 gemm_grid(DMODEL / BN, MROWS / BM);   // (8, 64)
    dim3 gemm_block(256);

    // Q/K/V projections
    sgemm_kernel<<<gemm_grid, gemm_block>>>(x, Wq, Qp, nullptr, MROWS, DMODEL, DMODEL);
    sgemm_kernel<<<gemm_grid, gemm_block>>>(x, Wk, Kp, nullptr, MROWS, DMODEL, DMODEL);
    sgemm_kernel<<<gemm_grid, gemm_block>>>(x, Wv, Vp, nullptr, MROWS, DMODEL, DMODEL);

    // Causal flash attention
    dim3 attn_grid(SEQ / 128, BATCH * NHEAD);  // (16, 64)
    attn_kernel<<<attn_grid, 128>>>();

    // Output projection + bias
    sgemm_kernel<<<gemm_grid, gemm_block>>>(Cp, Wo, out, bo, MROWS, DMODEL, DMODEL);
}

// round 3
// speedup vs baseline: 1.2908x; 1.2908x over previous
#include <cuda_runtime.h>
#include <cuda_bf16.h>
#include <cstdint>

// Problem constants
#define BATCH 4
#define SEQ   2048
#define DMODEL 1024
#define NHEAD 16
#define HDIM  64
#define MROWS (BATCH * SEQ)          // 8192
#define SOFTMAX_SCALE 0.125f         // 1/sqrt(64)

// ---------------------------------------------------------------------------
// Scratch (static device globals -- no allocation allowed)
// ---------------------------------------------------------------------------
__device__ float g_Q[MROWS * DMODEL];
__device__ float g_K[MROWS * DMODEL];
__device__ float g_V[MROWS * DMODEL];
__device__ float g_C[MROWS * DMODEL];
__device__ __nv_bfloat16 g_xhi[MROWS * DMODEL];   // also reused for C split
__device__ __nv_bfloat16 g_xlo[MROWS * DMODEL];
__device__ __nv_bfloat16 g_wthi[DMODEL * DMODEL]; // W^T hi
__device__ __nv_bfloat16 g_wtlo[DMODEL * DMODEL]; // W^T lo

// ---------------------------------------------------------------------------
// PTX helpers (sm_80+ only: mma.sync / ldmatrix / cp.async)
// ---------------------------------------------------------------------------
__device__ __forceinline__ uint32_t smem_u32(const void* p) {
    uint32_t a;
    asm("{ .reg .u64 t; cvta.to.shared.u64 t, %1; cvt.u32.u64 %0, t; }"
        : "=r"(a) : "l"(p));
    return a;
}

__device__ __forceinline__ void cp_async16(uint32_t dst, const void* src) {
    asm volatile("cp.async.cg.shared.global [%0], [%1], 16;"
                 :: "r"(dst), "l"(__cvta_generic_to_global(src)) : "memory");
}
__device__ __forceinline__ void cp_commit() {
    asm volatile("cp.async.commit_group;" ::: "memory");
}

__device__ __forceinline__ void ldsm4(uint32_t (&r)[4], uint32_t addr) {
    asm volatile("ldmatrix.sync.aligned.m8n8.x4.shared.b16 {%0,%1,%2,%3}, [%4];"
                 : "=r"(r[0]), "=r"(r[1]), "=r"(r[2]), "=r"(r[3]) : "r"(addr));
}

__device__ __forceinline__ void mma16816(float (&d)[4], const uint32_t (&a)[4],
                                         uint32_t b0, uint32_t b1) {
    asm volatile(
        "mma.sync.aligned.m16n8k16.row.col.f32.bf16.bf16.f32 "
        "{%0,%1,%2,%3}, {%4,%5,%6,%7}, {%8,%9}, {%0,%1,%2,%3};"
        : "+f"(d[0]), "+f"(d[1]), "+f"(d[2]), "+f"(d[3])
        : "r"(a[0]), "r"(a[1]), "r"(a[2]), "r"(a[3]), "r"(b0), "r"(b1));
}

// ---------------------------------------------------------------------------
// Split fp32 -> (hi, lo) bf16, 4 elements per thread
// ---------------------------------------------------------------------------
__global__ __launch_bounds__(256)
void split_kernel(const float* __restrict__ in, __nv_bfloat16* __restrict__ hi,
                  __nv_bfloat16* __restrict__ lo, int n4)
{
    int i = blockIdx.x * blockDim.x + threadIdx.x;
    if (i >= n4) return;
    float4 v = *(const float4*)(in + (size_t)i * 4);
    __nv_bfloat16 h0 = __float2bfloat16(v.x);
    __nv_bfloat16 h1 = __float2bfloat16(v.y);
    __nv_bfloat16 h2 = __float2bfloat16(v.z);
    __nv_bfloat16 h3 = __float2bfloat16(v.w);
    __nv_bfloat16 l0 = __float2bfloat16(v.x - __bfloat162float(h0));
    __nv_bfloat16 l1 = __float2bfloat16(v.y - __bfloat162float(h1));
    __nv_bfloat16 l2 = __float2bfloat16(v.z - __bfloat162float(h2));
    __nv_bfloat16 l3 = __float2bfloat16(v.w - __bfloat162float(h3));
    __nv_bfloat162 hp0 = {h0, h1}, hp1 = {h2, h3};
    __nv_bfloat162 lp0 = {l0, l1}, lp1 = {l2, l3};
    uint2 hv = {*(uint32_t*)&hp0, *(uint32_t*)&hp1};
    uint2 lv = {*(uint32_t*)&lp0, *(uint32_t*)&lp1};
    *(uint2*)(hi + (size_t)i * 4) = hv;
    *(uint2*)(lo + (size_t)i * 4) = lv;
}

// ---------------------------------------------------------------------------
// Transpose + split: W[K=1024][N=1024] fp32 -> WT_hi/lo [N][K] bf16
// ---------------------------------------------------------------------------
__global__ __launch_bounds__(256)
void tsplit_kernel(const float* __restrict__ W, __nv_bfloat16* __restrict__ Thi,
                   __nv_bfloat16* __restrict__ Tlo)
{
    __shared__ float t[32][33];
    const int n0 = blockIdx.x * 32;
    const int k0 = blockIdx.y * 32;
    const int tx = threadIdx.x;   // 0..31
    const int ty = threadIdx.y;   // 0..7
    #pragma unroll
    for (int i = 0; i < 4; ++i)
        t[ty + 8 * i][tx] = W[(size_t)(k0 + ty + 8 * i) * DMODEL + n0 + tx];
    __syncthreads();
    #pragma unroll
    for (int i = 0; i < 4; ++i) {
        float v = t[tx][ty + 8 * i];
        __nv_bfloat16 h = __float2bfloat16(v);
        __nv_bfloat16 l = __float2bfloat16(v - __bfloat162float(h));
        size_t o = (size_t)(n0 + ty + 8 * i) * DMODEL + k0 + tx;
        Thi[o] = h;
        Tlo[o] = l;
    }
}

// ---------------------------------------------------------------------------
// mma.sync bf16 hi/lo-split GEMM: C[M,N] = A[M,K] @ WT[N,K]^T (+ bias)
// 128x128 tile, BK=32, 8 warps (2m x 4n), warp tile 64x32, m16n8k16 MMAs.
// Smem rows padded to 80B for conflict-free ldmatrix. 2-stage cp.async pipe.
// ---------------------------------------------------------------------------
#define GBK    32
#define ROWB   80                       // 40 bf16 per padded row (32 used)
#define TILE_B (128 * ROWB)             // 10240
#define STAGE_B (4 * TILE_B)            // Ahi, Alo, Bhi, Blo = 40960
#define NCH    (DMODEL / GBK)           // 32
#define GEMM_SMEM (2 * STAGE_B)         // 81920

__global__ __launch_bounds__(256)
void gemm_mma_kernel(const __nv_bfloat16* __restrict__ Ahi,
                     const __nv_bfloat16* __restrict__ Alo,
                     const __nv_bfloat16* __restrict__ Bhi,
                     const __nv_bfloat16* __restrict__ Blo,
                     float* __restrict__ C, const float* __restrict__ bias)
{
    extern __shared__ char sm[];
    const uint32_t sbase = smem_u32(sm);

    const int tid = threadIdx.x;
    const int wid = tid >> 5;
    const int lane = tid & 31;
    const int warp_m = wid & 1;          // 0..1  (x64 rows)
    const int warp_n = wid >> 1;         // 0..3  (x32 cols)
    const int n0 = blockIdx.x * 128;
    const int m0 = blockIdx.y * 128;

    float acc[4][4][4];
    #pragma unroll
    for (int mt = 0; mt < 4; ++mt)
        #pragma unroll
        for (int nt = 0; nt < 4; ++nt)
            #pragma unroll
            for (int i = 0; i < 4; ++i) acc[mt][nt][i] = 0.f;

    // ---- async stage loader: 4 tiles x 128 rows x 2 segs(16B) = 2048 ops/8 = 8/thread
    auto issue = [&](int c) {
        const int stage = c & 1;
        const uint32_t dstb = sbase + stage * STAGE_B;
        const int k0 = c * GBK;
        #pragma unroll
        for (int t = 0; t < 8; ++t) {
            const int idx = t * 256 + tid;        // 0..2047
            const int tile = idx >> 9;            // 0..3
            const int row = (idx >> 2) & 127;
            const int seg = idx & 3;
            const __nv_bfloat16* src;
            if (tile == 0)      src = Ahi + (size_t)(m0 + row) * DMODEL;
            else if (tile == 1) src = Alo + (size_t)(m0 + row) * DMODEL;
            else if (tile == 2) src = Bhi + (size_t)(n0 + row) * DMODEL;
            else                src = Blo + (size_t)(n0 + row) * DMODEL;
            const uint32_t dst = dstb + tile * TILE_B + row * ROWB + seg * 16;
            cp_async16(dst, src + k0 + seg * 8);
        }
        cp_commit();
    };

    issue(0);

    for (int c = 0; c < NCH; ++c) {
        if (c + 1 < NCH) {
            issue(c + 1);
            asm volatile("cp.async.wait_group 1;" ::: "memory");
        } else {
            asm volatile("cp.async.wait_group 0;" ::: "memory");
        }
        __syncthreads();

        const uint32_t sb = sbase + (c & 1) * STAGE_B;

        #pragma unroll
        for (int ks = 0; ks < 2; ++ks) {
            // A fragments (hi and lo), 4 m-tiles each
            uint32_t ahi[4][4], alo[4][4];
            const int arow_base = warp_m * 64 + (lane & 15);
            const int acolb = ks * 32 + ((lane >> 4) << 4);   // byte offset in row
            #pragma unroll
            for (int mt = 0; mt < 4; ++mt) {
                const uint32_t off = (uint32_t)(arow_base + mt * 16) * ROWB + acolb;
                ldsm4(ahi[mt], sb + 0 * TILE_B + off);
                ldsm4(alo[mt], sb + 1 * TILE_B + off);
            }
            // B fragments (hi and lo), 4 n-tiles via two x4 loads each
            uint32_t bhi[4][2], blo[4][2];
            const int brow_base = warp_n * 32 + ((lane >> 4) & 1) * 8 + (lane & 7);
            const int bcolb = ks * 32 + ((lane >> 3) & 1) * 16;
            #pragma unroll
            for (int p = 0; p < 2; ++p) {
                const uint32_t off = (uint32_t)(brow_base + p * 16) * ROWB + bcolb;
                uint32_t r4[4];
                ldsm4(r4, sb + 2 * TILE_B + off);
                bhi[2 * p][0] = r4[0]; bhi[2 * p][1] = r4[1];
                bhi[2 * p + 1][0] = r4[2]; bhi[2 * p + 1][1] = r4[3];
                ldsm4(r4, sb + 3 * TILE_B + off);
                blo[2 * p][0] = r4[0]; blo[2 * p][1] = r4[1];
                blo[2 * p + 1][0] = r4[2]; blo[2 * p + 1][1] = r4[3];
            }
            // 3-pass split MMA
            #pragma unroll
            for (int mt = 0; mt < 4; ++mt)
                #pragma unroll
                for (int nt = 0; nt < 4; ++nt) {
                    mma16816(acc[mt][nt], ahi[mt], bhi[nt][0], bhi[nt][1]);
                    mma16816(acc[mt][nt], alo[mt], bhi[nt][0], bhi[nt][1]);
                    mma16816(acc[mt][nt], ahi[mt], blo[nt][0], blo[nt][1]);
                }
        }
        __syncthreads();
    }

    // ---- epilogue: direct float2 stores
    const int g = lane >> 2;
    const int t4 = lane & 3;
    #pragma unroll
    for (int mt = 0; mt < 4; ++mt) {
        #pragma unroll
        for (int nt = 0; nt < 4; ++nt) {
            const int col = n0 + warp_n * 32 + nt * 8 + t4 * 2;
            const int r0 = m0 + warp_m * 64 + mt * 16 + g;
            float2 v0 = { acc[mt][nt][0], acc[mt][nt][1] };
            float2 v1 = { acc[mt][nt][2], acc[mt][nt][3] };
            if (bias) {
                const float b0 = bias[col], b1 = bias[col + 1];
                v0.x += b0; v0.y += b1;
                v1.x += b0; v1.y += b1;
            }
            *(float2*)&C[(size_t)r0 * DMODEL + col] = v0;
            *(float2*)&C[(size_t)(r0 + 8) * DMODEL + col] = v1;
        }
    }
}

// ---------------------------------------------------------------------------
// Flash attention (causal), fp32 — unchanged
// ---------------------------------------------------------------------------
__global__ __launch_bounds__(128)
void attn_kernel()
{
    __shared__ float Ks[64][64];
    __shared__ float Vs[64][64];

    const int qt = blockIdx.x;
    const int bh = blockIdx.y;
    const int b  = bh / NHEAD;
    const int h  = bh % NHEAD;
    const int q0 = qt * 128;
    const int r  = threadIdx.x;
    const int qg = q0 + r;

    const size_t head_off = (size_t)h * HDIM;
    const float* Qrow = g_Q + ((size_t)(b * SEQ + qg)) * DMODEL + head_off;

    float q[HDIM];
    #pragma unroll
    for (int d = 0; d < HDIM; d += 4) {
        float4 t = *(const float4*)(Qrow + d);
        q[d] = t.x; q[d + 1] = t.y; q[d + 2] = t.z; q[d + 3] = t.w;
    }

    float acc[HDIM];
    #pragma unroll
    for (int d = 0; d < HDIM; ++d) acc[d] = 0.f;
    float m = -1e30f;
    float l = 0.f;

    const int ntiles = q0 / 64 + 2;

    for (int jt = 0; jt < ntiles; ++jt) {
        const int j0 = jt * 64;
        const float* Kg = g_K + ((size_t)(b * SEQ + j0)) * DMODEL + head_off;
        const float* Vg = g_V + ((size_t)(b * SEQ + j0)) * DMODEL + head_off;

        __syncthreads();
        #pragma unroll
        for (int i = 0; i < 8; ++i) {
            const int idx = r + 128 * i;
            const int row = idx >> 4;
            const int c4  = (idx & 15) * 4;
            *(float4*)&Ks[row][c4] = *(const float4*)(Kg + (size_t)row * DMODEL + c4);
            *(float4*)&Vs[row][c4] = *(const float4*)(Vg + (size_t)row * DMODEL + c4);
        }
        __syncthreads();

        #pragma unroll
        for (int sub = 0; sub < 4; ++sub) {
            float s[16];
            #pragma unroll
            for (int jj = 0; jj < 16; ++jj) {
                const int j = sub * 16 + jj;
                float sv = 0.f;
                #pragma unroll
                for (int d = 0; d < HDIM; ++d)
                    sv += q[d] * Ks[j][d];
                const int kg = j0 + j;
                s[jj] = (kg <= qg) ? sv * SOFTMAX_SCALE : -1e30f;
            }
            float smax = s[0];
            #pragma unroll
            for (int jj = 1; jj < 16; ++jj) smax = fmaxf(smax, s[jj]);
            const float mnew = fmaxf(m, smax);
            const float corr = __expf(m - mnew);
            l *= corr;
            #pragma unroll
            for (int d = 0; d < HDIM; ++d) acc[d] *= corr;
            #pragma unroll
            for (int jj = 0; jj < 16; ++jj) {
                const float p = __expf(s[jj] - mnew);
                l += p;
                const int j = sub * 16 + jj;
                #pragma unroll
                for (int d = 0; d < HDIM; ++d)
                    acc[d] += p * Vs[j][d];
            }
            m = mnew;
        }
    }

    const float inv = 1.f / l;
    float* Crow = g_C + ((size_t)(b * SEQ + qg)) * DMODEL + head_off;
    #pragma unroll
    for (int d = 0; d < HDIM; d += 4) {
        float4 t;
        t.x = acc[d] * inv;
        t.y = acc[d + 1] * inv;
        t.z = acc[d + 2] * inv;
        t.w = acc[d + 3] * inv;
        *(float4*)(Crow + d) = t;
    }
}

// ---------------------------------------------------------------------------
// Launch
// ---------------------------------------------------------------------------
extern "C" void kernel_launch(void* const* d_in, const int* in_sizes, int n_in,
                              void* d_out, int out_size)
{
    const float* x  = (const float*)d_in[0];
    const float* Wq = (const float*)d_in[1];
    const float* Wk = (const float*)d_in[2];
    const float* Wv = (const float*)d_in[3];
    const float* Wo = (const float*)d_in[4];
    const float* bo = (const float*)d_in[5];
    float* out = (float*)d_out;

    float *Qp, *Kp, *Vp, *Cp;
    __nv_bfloat16 *xhi, *xlo, *wthi, *wtlo;
    cudaGetSymbolAddress((void**)&Qp, g_Q);
    cudaGetSymbolAddress((void**)&Kp, g_K);
    cudaGetSymbolAddress((void**)&Vp, g_V);
    cudaGetSymbolAddress((void**)&Cp, g_C);
    cudaGetSymbolAddress((void**)&xhi, g_xhi);
    cudaGetSymbolAddress((void**)&xlo, g_xlo);
    cudaGetSymbolAddress((void**)&wthi, g_wthi);
    cudaGetSymbolAddress((void**)&wtlo, g_wtlo);

    cudaFuncSetAttribute(gemm_mma_kernel,
                         cudaFuncAttributeMaxDynamicSharedMemorySize, GEMM_SMEM);

    const int n4 = MROWS * DMODEL / 4;
    dim3 split_grid((n4 + 255) / 256);
    dim3 ts_grid(DMODEL / 32, DMODEL / 32);
    dim3 ts_block(32, 8);
    dim3 gg(DMODEL / 128, MROWS / 128);   // (8, 64)

    // split x once
    split_kernel<<<split_grid, 256>>>(x, xhi, xlo, n4);

    // Q, K, V projections
    tsplit_kernel<<<ts_grid, ts_block>>>(Wq, wthi, wtlo);
    gemm_mma_kernel<<<gg, 256, GEMM_SMEM>>>(xhi, xlo, wthi, wtlo, Qp, nullptr);
    tsplit_kernel<<<ts_grid, ts_block>>>(Wk, wthi, wtlo);
    gemm_mma_kernel<<<gg, 256, GEMM_SMEM>>>(xhi, xlo, wthi, wtlo, Kp, nullptr);
    tsplit_kernel<<<ts_grid, ts_block>>>(Wv, wthi, wtlo);
    gemm_mma_kernel<<<gg, 256, GEMM_SMEM>>>(xhi, xlo, wthi, wtlo, Vp, nullptr);

    // Causal flash attention
    dim3 attn_grid(SEQ / 128, BATCH * NHEAD);
    attn_kernel<<<attn_grid, 128>>>();

    // Output projection + bias (reuse x split buffers for C)
    split_kernel<<<split_grid, 256>>>(Cp, xhi, xlo, n4);
    tsplit_kernel<<<ts_grid, ts_block>>>(Wo, wthi, wtlo);
    gemm_mma_kernel<<<gg, 256, GEMM_SMEM>>>(xhi, xlo, wthi, wtlo, out, bo);
}

// round 4
// speedup vs baseline: 4.2156x; 3.2659x over previous
#include <cuda_runtime.h>
#include <cuda_bf16.h>
#include <cstdint>

// Problem constants
#define BATCH 4
#define SEQ   2048
#define DMODEL 1024
#define NHEAD 16
#define HDIM  64
#define MROWS (BATCH * SEQ)          // 8192
#define SOFTMAX_SCALE 0.125f         // 1/sqrt(64)

// ---------------------------------------------------------------------------
// Scratch (static device globals -- no allocation allowed)
// ---------------------------------------------------------------------------
__device__ __nv_bfloat16 g_xhi[MROWS * DMODEL];
__device__ __nv_bfloat16 g_xlo[MROWS * DMODEL];
__device__ __nv_bfloat16 g_wthi[DMODEL * DMODEL];
__device__ __nv_bfloat16 g_wtlo[DMODEL * DMODEL];
__device__ __nv_bfloat16 g_qhi[MROWS * DMODEL];
__device__ __nv_bfloat16 g_qlo[MROWS * DMODEL];
__device__ __nv_bfloat16 g_khi[MROWS * DMODEL];
__device__ __nv_bfloat16 g_klo[MROWS * DMODEL];
__device__ __nv_bfloat16 g_vhi[MROWS * DMODEL];
__device__ __nv_bfloat16 g_vlo[MROWS * DMODEL];
__device__ __nv_bfloat16 g_chi[MROWS * DMODEL];
__device__ __nv_bfloat16 g_clo[MROWS * DMODEL];

// ---------------------------------------------------------------------------
// PTX helpers (sm_80+ only)
// ---------------------------------------------------------------------------
__device__ __forceinline__ uint32_t smem_u32(const void* p) {
    uint32_t a;
    asm("{ .reg .u64 t; cvta.to.shared.u64 t, %1; cvt.u32.u64 %0, t; }"
        : "=r"(a) : "l"(p));
    return a;
}
__device__ __forceinline__ void cp_async16(uint32_t dst, const void* src) {
    asm volatile("cp.async.cg.shared.global [%0], [%1], 16;"
                 :: "r"(dst), "l"(__cvta_generic_to_global(src)) : "memory");
}
__device__ __forceinline__ void cp_commit() {
    asm volatile("cp.async.commit_group;" ::: "memory");
}
__device__ __forceinline__ void ldsm4(uint32_t (&r)[4], uint32_t addr) {
    asm volatile("ldmatrix.sync.aligned.m8n8.x4.shared.b16 {%0,%1,%2,%3}, [%4];"
                 : "=r"(r[0]), "=r"(r[1]), "=r"(r[2]), "=r"(r[3]) : "r"(addr));
}
__device__ __forceinline__ void ldsm4t(uint32_t (&r)[4], uint32_t addr) {
    asm volatile("ldmatrix.sync.aligned.m8n8.x4.trans.shared.b16 {%0,%1,%2,%3}, [%4];"
                 : "=r"(r[0]), "=r"(r[1]), "=r"(r[2]), "=r"(r[3]) : "r"(addr));
}
__device__ __forceinline__ void mma16816(float (&d)[4], const uint32_t (&a)[4],
                                         uint32_t b0, uint32_t b1) {
    asm volatile(
        "mma.sync.aligned.m16n8k16.row.col.f32.bf16.bf16.f32 "
        "{%0,%1,%2,%3}, {%4,%5,%6,%7}, {%8,%9}, {%0,%1,%2,%3};"
        : "+f"(d[0]), "+f"(d[1]), "+f"(d[2]), "+f"(d[3])
        : "r"(a[0]), "r"(a[1]), "r"(a[2]), "r"(a[3]), "r"(b0), "r"(b1));
}
// pack two floats into bf16x2 hi + residual lo
__device__ __forceinline__ void pack_hl(float a, float b, uint32_t& hi, uint32_t& lo) {
    __nv_bfloat162 h = __floats2bfloat162_rn(a, b);
    float ra = a - __bfloat162float(h.x);
    float rb = b - __bfloat162float(h.y);
    __nv_bfloat162 l = __floats2bfloat162_rn(ra, rb);
    hi = *(uint32_t*)&h;
    lo = *(uint32_t*)&l;
}

// ---------------------------------------------------------------------------
// Split fp32 -> (hi, lo) bf16 (input x only)
// ---------------------------------------------------------------------------
__global__ __launch_bounds__(256)
void split_kernel(const float* __restrict__ in, __nv_bfloat16* __restrict__ hi,
                  __nv_bfloat16* __restrict__ lo, int n4)
{
    int i = blockIdx.x * blockDim.x + threadIdx.x;
    if (i >= n4) return;
    float4 v = *(const float4*)(in + (size_t)i * 4);
    uint32_t h0, l0, h1, l1;
    pack_hl(v.x, v.y, h0, l0);
    pack_hl(v.z, v.w, h1, l1);
    uint2 hv = {h0, h1}, lv = {l0, l1};
    *(uint2*)(hi + (size_t)i * 4) = hv;
    *(uint2*)(lo + (size_t)i * 4) = lv;
}

// ---------------------------------------------------------------------------
// Transpose + split: W[K][N] fp32 -> WT_hi/lo [N][K] bf16
// ---------------------------------------------------------------------------
__global__ __launch_bounds__(256)
void tsplit_kernel(const float* __restrict__ W, __nv_bfloat16* __restrict__ Thi,
                   __nv_bfloat16* __restrict__ Tlo)
{
    __shared__ float t[32][33];
    const int n0 = blockIdx.x * 32;
    const int k0 = blockIdx.y * 32;
    const int tx = threadIdx.x;
    const int ty = threadIdx.y;
    #pragma unroll
    for (int i = 0; i < 4; ++i)
        t[ty + 8 * i][tx] = W[(size_t)(k0 + ty + 8 * i) * DMODEL + n0 + tx];
    __syncthreads();
    #pragma unroll
    for (int i = 0; i < 4; ++i) {
        float v = t[tx][ty + 8 * i];
        __nv_bfloat16 h = __float2bfloat16(v);
        __nv_bfloat16 l = __float2bfloat16(v - __bfloat162float(h));
        size_t o = (size_t)(n0 + ty + 8 * i) * DMODEL + k0 + tx;
        Thi[o] = h;
        Tlo[o] = l;
    }
}

// ---------------------------------------------------------------------------
// mma.sync bf16 hi/lo-split GEMM: out = A[M,K] @ WT[N,K]^T
// Epilogue either fp32 (+bias) or bf16 hi/lo split.
// ---------------------------------------------------------------------------
#define GBK    32
#define ROWB   80
#define TILE_B (128 * ROWB)
#define STAGE_B (4 * TILE_B)
#define NCH    (DMODEL / GBK)
#define GEMM_SMEM (2 * STAGE_B)

__global__ __launch_bounds__(256)
void gemm_mma_kernel(const __nv_bfloat16* __restrict__ Ahi,
                     const __nv_bfloat16* __restrict__ Alo,
                     const __nv_bfloat16* __restrict__ Bhi,
                     const __nv_bfloat16* __restrict__ Blo,
                     float* __restrict__ C, const float* __restrict__ bias,
                     __nv_bfloat16* __restrict__ Chi,
                     __nv_bfloat16* __restrict__ Clo)
{
    extern __shared__ char sm[];
    const uint32_t sbase = smem_u32(sm);

    const int tid = threadIdx.x;
    const int wid = tid >> 5;
    const int lane = tid & 31;
    const int warp_m = wid & 1;
    const int warp_n = wid >> 1;
    const int n0 = blockIdx.x * 128;
    const int m0 = blockIdx.y * 128;

    float acc[4][4][4];
    #pragma unroll
    for (int mt = 0; mt < 4; ++mt)
        #pragma unroll
        for (int nt = 0; nt < 4; ++nt)
            #pragma unroll
            for (int i = 0; i < 4; ++i) acc[mt][nt][i] = 0.f;

    auto issue = [&](int c) {
        const int stage = c & 1;
        const uint32_t dstb = sbase + stage * STAGE_B;
        const int k0 = c * GBK;
        #pragma unroll
        for (int t = 0; t < 8; ++t) {
            const int idx = t * 256 + tid;
            const int tile = idx >> 9;
            const int row = (idx >> 2) & 127;
            const int seg = idx & 3;
            const __nv_bfloat16* src;
            if (tile == 0)      src = Ahi + (size_t)(m0 + row) * DMODEL;
            else if (tile == 1) src = Alo + (size_t)(m0 + row) * DMODEL;
            else if (tile == 2) src = Bhi + (size_t)(n0 + row) * DMODEL;
            else                src = Blo + (size_t)(n0 + row) * DMODEL;
            const uint32_t dst = dstb + tile * TILE_B + row * ROWB + seg * 16;
            cp_async16(dst, src + k0 + seg * 8);
        }
        cp_commit();
    };

    issue(0);

    for (int c = 0; c < NCH; ++c) {
        if (c + 1 < NCH) {
            issue(c + 1);
            asm volatile("cp.async.wait_group 1;" ::: "memory");
        } else {
            asm volatile("cp.async.wait_group 0;" ::: "memory");
        }
        __syncthreads();

        const uint32_t sb = sbase + (c & 1) * STAGE_B;

        #pragma unroll
        for (int ks = 0; ks < 2; ++ks) {
            uint32_t ahi[4][4], alo[4][4];
            const int arow_base = warp_m * 64 + (lane & 15);
            const int acolb = ks * 32 + ((lane >> 4) << 4);
            #pragma unroll
            for (int mt = 0; mt < 4; ++mt) {
                const uint32_t off = (uint32_t)(arow_base + mt * 16) * ROWB + acolb;
                ldsm4(ahi[mt], sb + 0 * TILE_B + off);
                ldsm4(alo[mt], sb + 1 * TILE_B + off);
            }
            uint32_t bhi[4][2], blo[4][2];
            const int brow_base = warp_n * 32 + ((lane >> 4) & 1) * 8 + (lane & 7);
            const int bcolb = ks * 32 + ((lane >> 3) & 1) * 16;
            #pragma unroll
            for (int p = 0; p < 2; ++p) {
                const uint32_t off = (uint32_t)(brow_base + p * 16) * ROWB + bcolb;
                uint32_t r4[4];
                ldsm4(r4, sb + 2 * TILE_B + off);
                bhi[2 * p][0] = r4[0]; bhi[2 * p][1] = r4[1];
                bhi[2 * p + 1][0] = r4[2]; bhi[2 * p + 1][1] = r4[3];
                ldsm4(r4, sb + 3 * TILE_B + off);
                blo[2 * p][0] = r4[0]; blo[2 * p][1] = r4[1];
                blo[2 * p + 1][0] = r4[2]; blo[2 * p + 1][1] = r4[3];
            }
            #pragma unroll
            for (int mt = 0; mt < 4; ++mt)
                #pragma unroll
                for (int nt = 0; nt < 4; ++nt) {
                    mma16816(acc[mt][nt], ahi[mt], bhi[nt][0], bhi[nt][1]);
                    mma16816(acc[mt][nt], alo[mt], bhi[nt][0], bhi[nt][1]);
                    mma16816(acc[mt][nt], ahi[mt], blo[nt][0], blo[nt][1]);
                }
        }
        __syncthreads();
    }

    const int g = lane >> 2;
    const int t4 = lane & 3;
    if (Chi) {
        #pragma unroll
        for (int mt = 0; mt < 4; ++mt)
            #pragma unroll
            for (int nt = 0; nt < 4; ++nt) {
                const int col = n0 + warp_n * 32 + nt * 8 + t4 * 2;
                const size_t r0 = (size_t)(m0 + warp_m * 64 + mt * 16 + g);
                uint32_t h0, l0, h1, l1;
                pack_hl(acc[mt][nt][0], acc[mt][nt][1], h0, l0);
                pack_hl(acc[mt][nt][2], acc[mt][nt][3], h1, l1);
                *(uint32_t*)&Chi[r0 * DMODEL + col] = h0;
                *(uint32_t*)&Clo[r0 * DMODEL + col] = l0;
                *(uint32_t*)&Chi[(r0 + 8) * DMODEL + col] = h1;
                *(uint32_t*)&Clo[(r0 + 8) * DMODEL + col] = l1;
            }
    } else {
        #pragma unroll
        for (int mt = 0; mt < 4; ++mt)
            #pragma unroll
            for (int nt = 0; nt < 4; ++nt) {
                const int col = n0 + warp_n * 32 + nt * 8 + t4 * 2;
                const size_t r0 = (size_t)(m0 + warp_m * 64 + mt * 16 + g);
                float2 v0 = { acc[mt][nt][0], acc[mt][nt][1] };
                float2 v1 = { acc[mt][nt][2], acc[mt][nt][3] };
                if (bias) {
                    const float b0 = bias[col], b1 = bias[col + 1];
                    v0.x += b0; v0.y += b1;
                    v1.x += b0; v1.y += b1;
                }
                *(float2*)&C[r0 * DMODEL + col] = v0;
                *(float2*)&C[(r0 + 8) * DMODEL + col] = v1;
            }
    }
}

// ---------------------------------------------------------------------------
// Tensor-core flash attention (causal), bf16 hi/lo inputs, fp32 softmax.
// grid (SEQ/128, B*H); 256 threads (8 warps x 16 q-rows).
// ---------------------------------------------------------------------------
#define AT_ROWB  144                       // 64 bf16 = 128B + 16B pad
#define QTILE_B  (128 * AT_ROWB)           // 18432
#define KTILE_B  (64 * AT_ROWB)            // 9216
#define KVSTG_B  (4 * KTILE_B)             // 36864
#define ATTN_SMEM (2 * QTILE_B + 2 * KVSTG_B)   // 110592

__global__ __launch_bounds__(256)
void attn_tc_kernel()
{
    extern __shared__ char sm[];
    const uint32_t sbase = smem_u32(sm);
    const uint32_t kvbase = sbase + 2 * QTILE_B;

    const int tid = threadIdx.x;
    const int w = tid >> 5;
    const int lane = tid & 31;
    const int qt = blockIdx.x;
    const int bh = blockIdx.y;
    const int b = bh >> 4;
    const int h = bh & 15;
    const int q0 = qt * 128;
    const size_t rowbase = (size_t)b * SEQ;
    const size_t hoff = (size_t)h * HDIM;

    const int ntiles = qt * 2 + 2;

    // ---- async loaders
    auto issueQ = [&]() {
        #pragma unroll
        for (int t = 0; t < 8; ++t) {
            const int idx = t * 256 + tid;       // 0..2047
            const int ten = idx >> 10;           // 0 hi, 1 lo
            const int row = (idx >> 3) & 127;
            const int seg = idx & 7;
            const __nv_bfloat16* src = (ten == 0 ? g_qhi : g_qlo) +
                (rowbase + q0 + row) * DMODEL + hoff + seg * 8;
            cp_async16(sbase + ten * QTILE_B + row * AT_ROWB + seg * 16, src);
        }
    };
    auto issueKV = [&](int jt, int stage) {
        const int j0 = jt * 64;
        #pragma unroll
        for (int t = 0; t < 8; ++t) {
            const int idx = t * 256 + tid;       // 0..2047
            const int ten = idx >> 9;            // 0 Khi 1 Klo 2 Vhi 3 Vlo
            const int row = (idx >> 3) & 63;
            const int seg = idx & 7;
            const __nv_bfloat16* base;
            if (ten == 0)      base = g_khi;
            else if (ten == 1) base = g_klo;
            else if (ten == 2) base = g_vhi;
            else               base = g_vlo;
            const __nv_bfloat16* src = base + (rowbase + j0 + row) * DMODEL + hoff + seg * 8;
            cp_async16(kvbase + stage * KVSTG_B + ten * KTILE_B + row * AT_ROWB + seg * 16, src);
        }
        cp_commit();
    };

    issueQ();
    issueKV(0, 0);        // group #0 (Q + KV0)
    if (ntiles > 1) issueKV(1, 1);   // group #1

    // ---- per-warp state
    float O[8][4];
    #pragma unroll
    for (int nt = 0; nt < 8; ++nt)
        #pragma unroll
        for (int i = 0; i < 4; ++i) O[nt][i] = 0.f;
    float m0 = -1e30f, m1 = -1e30f, l0 = 0.f, l1 = 0.f;

    uint32_t qhi[4][4], qlo[4][4];
    const int qg0 = q0 + w * 16 + (lane >> 2);

    for (int jt = 0; jt < ntiles; ++jt) {
        if (jt + 1 < ntiles)
            asm volatile("cp.async.wait_group 1;" ::: "memory");
        else
            asm volatile("cp.async.wait_group 0;" ::: "memory");
        __syncthreads();

        if (jt == 0) {
            // hoist Q fragments (constant across k-tiles)
            const int arow = w * 16 + (lane & 15);
            #pragma unroll
            for (int ks = 0; ks < 4; ++ks) {
                const uint32_t off = (uint32_t)arow * AT_ROWB + ks * 32 + ((lane >> 4) << 4);
                ldsm4(qhi[ks], sbase + off);
                ldsm4(qlo[ks], sbase + QTILE_B + off);
            }
        }

        const int j0 = jt * 64;
        const bool active = (j0 <= q0 + w * 16 + 15);
        if (active) {
            const uint32_t kb = kvbase + (jt & 1) * KVSTG_B;
            const bool need_mask = (j0 + 63 > q0 + w * 16);

            // ---- S = Q K^T (3-pass hi/lo)
            float S[8][4];
            #pragma unroll
            for (int nt = 0; nt < 8; ++nt)
                #pragma unroll
                for (int i = 0; i < 4; ++i) S[nt][i] = 0.f;

            #pragma unroll
            for (int ks = 0; ks < 4; ++ks) {
                const int brow = ((lane >> 4) & 1) * 8 + (lane & 7);
                const int bcolb = ks * 32 + ((lane >> 3) & 1) * 16;
                #pragma unroll
                for (int p = 0; p < 4; ++p) {
                    const uint32_t off = (uint32_t)(p * 16 + brow) * AT_ROWB + bcolb;
                    uint32_t kh[4], kl[4];
                    ldsm4(kh, kb + 0 * KTILE_B + off);
                    ldsm4(kl, kb + 1 * KTILE_B + off);
                    mma16816(S[2 * p],     qhi[ks], kh[0], kh[1]);
                    mma16816(S[2 * p + 1], qhi[ks], kh[2], kh[3]);
                    mma16816(S[2 * p],     qlo[ks], kh[0], kh[1]);
                    mma16816(S[2 * p + 1], qlo[ks], kh[2], kh[3]);
                    mma16816(S[2 * p],     qhi[ks], kl[0], kl[1]);
                    mma16816(S[2 * p + 1], qhi[ks], kl[2], kl[3]);
                }
            }

            // ---- online softmax in fragment
            float mx0 = -1e30f, mx1 = -1e30f;
            #pragma unroll
            for (int nt = 0; nt < 8; ++nt) {
                const int kgb = j0 + nt * 8 + (lane & 3) * 2;
                #pragma unroll
                for (int c = 0; c < 4; ++c) {
                    float v = S[nt][c] * SOFTMAX_SCALE;
                    if (need_mask) {
                        const int kg = kgb + (c & 1);
                        const int qg = qg0 + (c >> 1) * 8;
                        if (kg > qg) v = -1e30f;
                    }
                    S[nt][c] = v;
                }
                mx0 = fmaxf(mx0, fmaxf(S[nt][0], S[nt][1]));
                mx1 = fmaxf(mx1, fmaxf(S[nt][2], S[nt][3]));
            }
            mx0 = fmaxf(mx0, __shfl_xor_sync(0xffffffffu, mx0, 1));
            mx0 = fmaxf(mx0, __shfl_xor_sync(0xffffffffu, mx0, 2));
            mx1 = fmaxf(mx1, __shfl_xor_sync(0xffffffffu, mx1, 1));
            mx1 = fmaxf(mx1, __shfl_xor_sync(0xffffffffu, mx1, 2));
            const float mn0 = fmaxf(m0, mx0);
            const float mn1 = fmaxf(m1, mx1);
            const float c0 = __expf(m0 - mn0);
            const float c1 = __expf(m1 - mn1);
            float rs0 = 0.f, rs1 = 0.f;
            #pragma unroll
            for (int nt = 0; nt < 8; ++nt) {
                float p0 = __expf(S[nt][0] - mn0);
                float p1 = __expf(S[nt][1] - mn0);
                float p2 = __expf(S[nt][2] - mn1);
                float p3 = __expf(S[nt][3] - mn1);
                S[nt][0] = p0; S[nt][1] = p1; S[nt][2] = p2; S[nt][3] = p3;
                rs0 += p0 + p1;
                rs1 += p2 + p3;
            }
            rs0 += __shfl_xor_sync(0xffffffffu, rs0, 1);
            rs0 += __shfl_xor_sync(0xffffffffu, rs0, 2);
            rs1 += __shfl_xor_sync(0xffffffffu, rs1, 1);
            rs1 += __shfl_xor_sync(0xffffffffu, rs1, 2);
            l0 = l0 * c0 + rs0;
            l1 = l1 * c1 + rs1;
            #pragma unroll
            for (int nt = 0; nt < 8; ++nt) {
                O[nt][0] *= c0; O[nt][1] *= c0;
                O[nt][2] *= c1; O[nt][3] *= c1;
            }
            m0 = mn0; m1 = mn1;

            // ---- O += P V (3-pass hi/lo), V via ldmatrix.trans
            #pragma unroll
            for (int ks = 0; ks < 4; ++ks) {
                uint32_t aPhi[4], aPlo[4];
                pack_hl(S[2 * ks][0],     S[2 * ks][1],     aPhi[0], aPlo[0]);
                pack_hl(S[2 * ks][2],     S[2 * ks][3],     aPhi[1], aPlo[1]);
                pack_hl(S[2 * ks + 1][0], S[2 * ks + 1][1], aPhi[2], aPlo[2]);
                pack_hl(S[2 * ks + 1][2], S[2 * ks + 1][3], aPhi[3], aPlo[3]);
                const int mI = lane >> 3;
                const int r = lane & 7;
                #pragma unroll
                for (int p = 0; p < 4; ++p) {
                    const uint32_t off = (uint32_t)(ks * 16 + (mI & 1) * 8 + r) * AT_ROWB
                                       + p * 32 + (mI >> 1) * 16;
                    uint32_t vh[4], vl[4];
                    ldsm4t(vh, kb + 2 * KTILE_B + off);
                    ldsm4t(vl, kb + 3 * KTILE_B + off);
                    mma16816(O[2 * p],     aPhi, vh[0], vh[1]);
                    mma16816(O[2 * p + 1], aPhi, vh[2], vh[3]);
                    mma16816(O[2 * p],     aPlo, vh[0], vh[1]);
                    mma16816(O[2 * p + 1], aPlo, vh[2], vh[3]);
                    mma16816(O[2 * p],     aPhi, vl[0], vl[1]);
                    mma16816(O[2 * p + 1], aPhi, vl[2], vl[3]);
                }
            }
        }
        __syncthreads();
        if (jt + 2 < ntiles) issueKV(jt + 2, jt & 1);
    }

    // ---- epilogue: normalize, split to bf16 hi/lo context
    const float inv0 = 1.f / l0;
    const float inv1 = 1.f / l1;
    const size_t r0 = rowbase + q0 + w * 16 + (lane >> 2);
    #pragma unroll
    for (int nt = 0; nt < 8; ++nt) {
        const int col = (int)hoff + nt * 8 + (lane & 3) * 2;
        uint32_t h0, l0p, h1, l1p;
        pack_hl(O[nt][0] * inv0, O[nt][1] * inv0, h0, l0p);
        pack_hl(O[nt][2] * inv1, O[nt][3] * inv1, h1, l1p);
        *(uint32_t*)&g_chi[r0 * DMODEL + col] = h0;
        *(uint32_t*)&g_clo[r0 * DMODEL + col] = l0p;
        *(uint32_t*)&g_chi[(r0 + 8) * DMODEL + col] = h1;
        *(uint32_t*)&g_clo[(r0 + 8) * DMODEL + col] = l1p;
    }
}

// ---------------------------------------------------------------------------
// Launch
// ---------------------------------------------------------------------------
extern "C" void kernel_launch(void* const* d_in, const int* in_sizes, int n_in,
                              void* d_out, int out_size)
{
    const float* x  = (const float*)d_in[0];
    const float* Wq = (const float*)d_in[1];
    const float* Wk = (const float*)d_in[2];
    const float* Wv = (const float*)d_in[3];
    const float* Wo = (const float*)d_in[4];
    const float* bo = (const float*)d_in[5];
    float* out = (float*)d_out;

    __nv_bfloat16 *xhi, *xlo, *wthi, *wtlo, *qhi, *qlo, *khi, *klo, *vhi, *vlo, *chi, *clo;
    cudaGetSymbolAddress((void**)&xhi, g_xhi);
    cudaGetSymbolAddress((void**)&xlo, g_xlo);
    cudaGetSymbolAddress((void**)&wthi, g_wthi);
    cudaGetSymbolAddress((void**)&wtlo, g_wtlo);
    cudaGetSymbolAddress((void**)&qhi, g_qhi);
    cudaGetSymbolAddress((void**)&qlo, g_qlo);
    cudaGetSymbolAddress((void**)&khi, g_khi);
    cudaGetSymbolAddress((void**)&klo, g_klo);
    cudaGetSymbolAddress((void**)&vhi, g_vhi);
    cudaGetSymbolAddress((void**)&vlo, g_vlo);
    cudaGetSymbolAddress((void**)&chi, g_chi);
    cudaGetSymbolAddress((void**)&clo, g_clo);

    cudaFuncSetAttribute(gemm_mma_kernel,
                         cudaFuncAttributeMaxDynamicSharedMemorySize, GEMM_SMEM);
    cudaFuncSetAttribute(attn_tc_kernel,
                         cudaFuncAttributeMaxDynamicSharedMemorySize, ATTN_SMEM);

    const int n4 = MROWS * DMODEL / 4;
    dim3 split_grid((n4 + 255) / 256);
    dim3 ts_grid(DMODEL / 32, DMODEL / 32);
    dim3 ts_block(32, 8);
    dim3 gg(DMODEL / 128, MROWS / 128);

    split_kernel<<<split_grid, 256>>>(x, xhi, xlo, n4);

    tsplit_kernel<<<ts_grid, ts_block>>>(Wq, wthi, wtlo);
    gemm_mma_kernel<<<gg, 256, GEMM_SMEM>>>(xhi, xlo, wthi, wtlo, nullptr, nullptr, qhi, qlo);
    tsplit_kernel<<<ts_grid, ts_block>>>(Wk, wthi, wtlo);
    gemm_mma_kernel<<<gg, 256, GEMM_SMEM>>>(xhi, xlo, wthi, wtlo, nullptr, nullptr, khi, klo);
    tsplit_kernel<<<ts_grid, ts_block>>>(Wv, wthi, wtlo);
    gemm_mma_kernel<<<gg, 256, GEMM_SMEM>>>(xhi, xlo, wthi, wtlo, nullptr, nullptr, vhi, vlo);

    dim3 attn_grid(SEQ / 128, BATCH * NHEAD);
    attn_tc_kernel<<<attn_grid, 256, ATTN_SMEM>>>();

    tsplit_kernel<<<ts_grid, ts_block>>>(Wo, wthi, wtlo);
    gemm_mma_kernel<<<gg, 256, GEMM_SMEM>>>(chi, clo, wthi, wtlo, out, bo, nullptr, nullptr);
}

// round 5
// speedup vs baseline: 6.2053x; 1.4720x over previous
#include <cuda_runtime.h>
#include <cuda_fp16.h>
#include <cstdint>

// Problem constants
#define BATCH 4
#define SEQ   2048
#define DMODEL 1024
#define NHEAD 16
#define HDIM  64
#define MROWS (BATCH * SEQ)          // 8192
#define SOFTMAX_SCALE 0.125f         // 1/sqrt(64)

// ---------------------------------------------------------------------------
// Scratch (static device globals)
// ---------------------------------------------------------------------------
__device__ __half g_xhi[MROWS * DMODEL];
__device__ __half g_xlo[MROWS * DMODEL];
__device__ __half g_wtqkv[3 * DMODEL * DMODEL];   // [3072][1024] = Wq^T;Wk^T;Wv^T (hi only)
__device__ __half g_wto[DMODEL * DMODEL];         // Wo^T (hi only)
__device__ __half g_qhi[MROWS * DMODEL];
__device__ __half g_qlo[MROWS * DMODEL];
__device__ __half g_kh[MROWS * DMODEL];
__device__ __half g_vh[MROWS * DMODEL];
__device__ __half g_chi[MROWS * DMODEL];
__device__ __half g_clo[MROWS * DMODEL];

// ---------------------------------------------------------------------------
// PTX helpers (sm_80+ only)
// ---------------------------------------------------------------------------
__device__ __forceinline__ uint32_t smem_u32(const void* p) {
    uint32_t a;
    asm("{ .reg .u64 t; cvta.to.shared.u64 t, %1; cvt.u32.u64 %0, t; }"
        : "=r"(a) : "l"(p));
    return a;
}
__device__ __forceinline__ void cp_async16(uint32_t dst, const void* src) {
    asm volatile("cp.async.cg.shared.global [%0], [%1], 16;"
                 :: "r"(dst), "l"(__cvta_generic_to_global(src)) : "memory");
}
__device__ __forceinline__ void cp_commit() {
    asm volatile("cp.async.commit_group;" ::: "memory");
}
__device__ __forceinline__ void ldsm4(uint32_t (&r)[4], uint32_t addr) {
    asm volatile("ldmatrix.sync.aligned.m8n8.x4.shared.b16 {%0,%1,%2,%3}, [%4];"
                 : "=r"(r[0]), "=r"(r[1]), "=r"(r[2]), "=r"(r[3]) : "r"(addr));
}
__device__ __forceinline__ void ldsm4t(uint32_t (&r)[4], uint32_t addr) {
    asm volatile("ldmatrix.sync.aligned.m8n8.x4.trans.shared.b16 {%0,%1,%2,%3}, [%4];"
                 : "=r"(r[0]), "=r"(r[1]), "=r"(r[2]), "=r"(r[3]) : "r"(addr));
}
__device__ __forceinline__ void mma16816(float (&d)[4], const uint32_t (&a)[4],
                                         uint32_t b0, uint32_t b1) {
    asm volatile(
        "mma.sync.aligned.m16n8k16.row.col.f32.f16.f16.f32 "
        "{%0,%1,%2,%3}, {%4,%5,%6,%7}, {%8,%9}, {%0,%1,%2,%3};"
        : "+f"(d[0]), "+f"(d[1]), "+f"(d[2]), "+f"(d[3])
        : "r"(a[0]), "r"(a[1]), "r"(a[2]), "r"(a[3]), "r"(b0), "r"(b1));
}
__device__ __forceinline__ uint32_t pack_h(float a, float b) {
    __half2 h = __floats2half2_rn(a, b);
    return *(uint32_t*)&h;
}
__device__ __forceinline__ void pack_hl(float a, float b, uint32_t& hi, uint32_t& lo) {
    __half2 h = __floats2half2_rn(a, b);
    float ra = a - __low2float(h);
    float rb = b - __high2float(h);
    __half2 l = __floats2half2_rn(ra, rb);
    hi = *(uint32_t*)&h;
    lo = *(uint32_t*)&l;
}

// ---------------------------------------------------------------------------
// Split fp32 x -> (hi, lo) fp16
// ---------------------------------------------------------------------------
__global__ __launch_bounds__(256)
void split_kernel(const float* __restrict__ in, int n4)
{
    int i = blockIdx.x * blockDim.x + threadIdx.x;
    if (i >= n4) return;
    float4 v = *(const float4*)(in + (size_t)i * 4);
    uint32_t h0, l0, h1, l1;
    pack_hl(v.x, v.y, h0, l0);
    pack_hl(v.z, v.w, h1, l1);
    uint2 hv = {h0, h1}, lv = {l0, l1};
    *(uint2*)&g_xhi[(size_t)i * 4] = hv;
    *(uint2*)&g_xlo[(size_t)i * 4] = lv;
}

// ---------------------------------------------------------------------------
// Transpose all 4 weights (hi only): W[K][N] fp32 -> WT[N][K] fp16
// grid (32, 32, 4): z = 0..2 -> wtqkv rows z*1024.., z = 3 -> wto
// ---------------------------------------------------------------------------
__global__ __launch_bounds__(256)
void tsplit4_kernel(const float* __restrict__ W0, const float* __restrict__ W1,
                    const float* __restrict__ W2, const float* __restrict__ W3)
{
    __shared__ float t[32][33];
    const int z = blockIdx.z;
    const float* W = (z == 0) ? W0 : (z == 1) ? W1 : (z == 2) ? W2 : W3;
    __half* dst = (z < 3) ? (g_wtqkv + (size_t)z * DMODEL * DMODEL) : g_wto;

    const int n0 = blockIdx.x * 32;
    const int k0 = blockIdx.y * 32;
    const int tx = threadIdx.x;
    const int ty = threadIdx.y;
    #pragma unroll
    for (int i = 0; i < 4; ++i)
        t[ty + 8 * i][tx] = W[(size_t)(k0 + ty + 8 * i) * DMODEL + n0 + tx];
    __syncthreads();
    #pragma unroll
    for (int i = 0; i < 4; ++i)
        dst[(size_t)(n0 + ty + 8 * i) * DMODEL + k0 + tx] = __float2half_rn(t[tx][ty + 8 * i]);
}

// ---------------------------------------------------------------------------
// fp16 2-pass GEMM: out = A[M,K] @ BT[N,K]^T;  A split hi/lo, B hi only.
// 128x128 tile, BK=32, 8 warps (2m x 4n), 2-stage cp.async pipeline.
// mode 1 (QKV fused): grid.x = 24, outputs to g_qhi/g_qlo (mat 0),
//                     g_kh (mat 1), g_vh (mat 2), selected by n-block.
// mode 0 (O proj):    grid.x = 8, fp32 out + bias.
// ---------------------------------------------------------------------------
#define GBK    32
#define ROWB   80
#define TILE_B (128 * ROWB)
#define STAGE_B (3 * TILE_B)            // Ahi, Alo, Bh
#define NCH    (DMODEL / GBK)
#define GEMM_SMEM (2 * STAGE_B)         // 61440

__global__ __launch_bounds__(256)
void gemm_mma_kernel(const __half* __restrict__ Ahi, const __half* __restrict__ Alo,
                     const __half* __restrict__ Bh,
                     float* __restrict__ C, const float* __restrict__ bias, int qkv_mode)
{
    extern __shared__ char sm[];
    const uint32_t sbase = smem_u32(sm);

    const int tid = threadIdx.x;
    const int wid = tid >> 5;
    const int lane = tid & 31;
    const int warp_m = wid & 1;
    const int warp_n = wid >> 1;
    const int n0 = blockIdx.x * 128;     // global row into BT (0..3071 for QKV)
    const int m0 = blockIdx.y * 128;

    float acc[4][4][4];
    #pragma unroll
    for (int mt = 0; mt < 4; ++mt)
        #pragma unroll
        for (int nt = 0; nt < 4; ++nt)
            #pragma unroll
            for (int i = 0; i < 4; ++i) acc[mt][nt][i] = 0.f;

    auto issue = [&](int c) {
        const uint32_t dstb = sbase + (c & 1) * STAGE_B;
        const int k0 = c * GBK;
        #pragma unroll
        for (int t = 0; t < 6; ++t) {
            const int idx = t * 256 + tid;        // 0..1535
            const int tile = idx >> 9;            // 0 Ahi, 1 Alo, 2 Bh
            const int row = (idx >> 2) & 127;
            const int seg = idx & 3;
            const __half* src;
            if (tile == 0)      src = Ahi + (size_t)(m0 + row) * DMODEL;
            else if (tile == 1) src = Alo + (size_t)(m0 + row) * DMODEL;
            else                src = Bh + (size_t)(n0 + row) * DMODEL;
            cp_async16(dstb + tile * TILE_B + row * ROWB + seg * 16, src + k0 + seg * 8);
        }
        cp_commit();
    };

    issue(0);

    for (int c = 0; c < NCH; ++c) {
        if (c + 1 < NCH) {
            issue(c + 1);
            asm volatile("cp.async.wait_group 1;" ::: "memory");
        } else {
            asm volatile("cp.async.wait_group 0;" ::: "memory");
        }
        __syncthreads();

        const uint32_t sb = sbase + (c & 1) * STAGE_B;

        #pragma unroll
        for (int ks = 0; ks < 2; ++ks) {
            uint32_t ahi[4][4], alo[4][4];
            const int arow_base = warp_m * 64 + (lane & 15);
            const int acolb = ks * 32 + ((lane >> 4) << 4);
            #pragma unroll
            for (int mt = 0; mt < 4; ++mt) {
                const uint32_t off = (uint32_t)(arow_base + mt * 16) * ROWB + acolb;
                ldsm4(ahi[mt], sb + 0 * TILE_B + off);
                ldsm4(alo[mt], sb + 1 * TILE_B + off);
            }
            uint32_t bh[4][2];
            const int brow_base = warp_n * 32 + ((lane >> 4) & 1) * 8 + (lane & 7);
            const int bcolb = ks * 32 + ((lane >> 3) & 1) * 16;
            #pragma unroll
            for (int p = 0; p < 2; ++p) {
                const uint32_t off = (uint32_t)(brow_base + p * 16) * ROWB + bcolb;
                uint32_t r4[4];
                ldsm4(r4, sb + 2 * TILE_B + off);
                bh[2 * p][0] = r4[0]; bh[2 * p][1] = r4[1];
                bh[2 * p + 1][0] = r4[2]; bh[2 * p + 1][1] = r4[3];
            }
            #pragma unroll
            for (int mt = 0; mt < 4; ++mt)
                #pragma unroll
                for (int nt = 0; nt < 4; ++nt) {
                    mma16816(acc[mt][nt], ahi[mt], bh[nt][0], bh[nt][1]);
                    mma16816(acc[mt][nt], alo[mt], bh[nt][0], bh[nt][1]);
                }
        }
        __syncthreads();
    }

    const int g = lane >> 2;
    const int t4 = lane & 3;
    if (qkv_mode) {
        const int mat = n0 >> 10;                 // 0 Q, 1 K, 2 V
        const int nloc = n0 & 1023;
        #pragma unroll
        for (int mt = 0; mt < 4; ++mt)
            #pragma unroll
            for (int nt = 0; nt < 4; ++nt) {
                const int col = nloc + warp_n * 32 + nt * 8 + t4 * 2;
                const size_t r0 = (size_t)(m0 + warp_m * 64 + mt * 16 + g);
                if (mat == 0) {
                    uint32_t h0, l0, h1, l1;
                    pack_hl(acc[mt][nt][0], acc[mt][nt][1], h0, l0);
                    pack_hl(acc[mt][nt][2], acc[mt][nt][3], h1, l1);
                    *(uint32_t*)&g_qhi[r0 * DMODEL + col] = h0;
                    *(uint32_t*)&g_qlo[r0 * DMODEL + col] = l0;
                    *(uint32_t*)&g_qhi[(r0 + 8) * DMODEL + col] = h1;
                    *(uint32_t*)&g_qlo[(r0 + 8) * DMODEL + col] = l1;
                } else {
                    __half* dst = (mat == 1) ? g_kh : g_vh;
                    *(uint32_t*)&dst[r0 * DMODEL + col] = pack_h(acc[mt][nt][0], acc[mt][nt][1]);
                    *(uint32_t*)&dst[(r0 + 8) * DMODEL + col] = pack_h(acc[mt][nt][2], acc[mt][nt][3]);
                }
            }
    } else {
        #pragma unroll
        for (int mt = 0; mt < 4; ++mt)
            #pragma unroll
            for (int nt = 0; nt < 4; ++nt) {
                const int col = n0 + warp_n * 32 + nt * 8 + t4 * 2;
                const size_t r0 = (size_t)(m0 + warp_m * 64 + mt * 16 + g);
                float2 v0 = { acc[mt][nt][0], acc[mt][nt][1] };
                float2 v1 = { acc[mt][nt][2], acc[mt][nt][3] };
                const float b0 = bias[col], b1 = bias[col + 1];
                v0.x += b0; v0.y += b1;
                v1.x += b0; v1.y += b1;
                *(float2*)&C[r0 * DMODEL + col] = v0;
                *(float2*)&C[(r0 + 8) * DMODEL + col] = v1;
            }
    }
}

// ---------------------------------------------------------------------------
// Tensor-core flash attention (causal), fp16 2-pass, fp32 softmax.
// grid (SEQ/128, B*H); 256 threads (8 warps x 16 q-rows).
// ---------------------------------------------------------------------------
#define AT_ROWB  144                        // 64 fp16 = 128B + 16B pad
#define QTILE_B  (128 * AT_ROWB)            // 18432
#define KTILE_B  (64 * AT_ROWB)             // 9216
#define KVSTG_B  (2 * KTILE_B)              // 18432 (Kh + Vh)
#define ATTN_SMEM (2 * QTILE_B + 2 * KVSTG_B)   // 73728

__global__ __launch_bounds__(256)
void attn_tc_kernel()
{
    extern __shared__ char sm[];
    const uint32_t sbase = smem_u32(sm);
    const uint32_t kvbase = sbase + 2 * QTILE_B;

    const int tid = threadIdx.x;
    const int w = tid >> 5;
    const int lane = tid & 31;
    const int qt = blockIdx.x;
    const int bh = blockIdx.y;
    const int b = bh >> 4;
    const int h = bh & 15;
    const int q0 = qt * 128;
    const size_t rowbase = (size_t)b * SEQ;
    const size_t hoff = (size_t)h * HDIM;

    const int ntiles = qt * 2 + 2;

    auto issueQ = [&]() {
        #pragma unroll
        for (int t = 0; t < 8; ++t) {
            const int idx = t * 256 + tid;       // 0..2047
            const int ten = idx >> 10;           // 0 hi, 1 lo
            const int row = (idx >> 3) & 127;
            const int seg = idx & 7;
            const __half* src = (ten == 0 ? g_qhi : g_qlo) +
                (rowbase + q0 + row) * DMODEL + hoff + seg * 8;
            cp_async16(sbase + ten * QTILE_B + row * AT_ROWB + seg * 16, src);
        }
    };
    auto issueKV = [&](int jt, int stage) {
        const int j0 = jt * 64;
        #pragma unroll
        for (int t = 0; t < 4; ++t) {
            const int idx = t * 256 + tid;       // 0..1023
            const int ten = idx >> 9;            // 0 Kh, 1 Vh
            const int row = (idx >> 3) & 63;
            const int seg = idx & 7;
            const __half* src = (ten == 0 ? g_kh : g_vh) +
                (rowbase + j0 + row) * DMODEL + hoff + seg * 8;
            cp_async16(kvbase + stage * KVSTG_B + ten * KTILE_B + row * AT_ROWB + seg * 16, src);
        }
        cp_commit();
    };

    issueQ();
    issueKV(0, 0);
    if (ntiles > 1) issueKV(1, 1);

    float O[8][4];
    #pragma unroll
    for (int nt = 0; nt < 8; ++nt)
        #pragma unroll
        for (int i = 0; i < 4; ++i) O[nt][i] = 0.f;
    float m0 = -1e30f, m1 = -1e30f, l0 = 0.f, l1 = 0.f;

    uint32_t qhi[4][4], qlo[4][4];
    const int qg0 = q0 + w * 16 + (lane >> 2);

    for (int jt = 0; jt < ntiles; ++jt) {
        if (jt + 1 < ntiles)
            asm volatile("cp.async.wait_group 1;" ::: "memory");
        else
            asm volatile("cp.async.wait_group 0;" ::: "memory");
        __syncthreads();

        if (jt == 0) {
            const int arow = w * 16 + (lane & 15);
            #pragma unroll
            for (int ks = 0; ks < 4; ++ks) {
                const uint32_t off = (uint32_t)arow * AT_ROWB + ks * 32 + ((lane >> 4) << 4);
                ldsm4(qhi[ks], sbase + off);
                ldsm4(qlo[ks], sbase + QTILE_B + off);
            }
        }

        const int j0 = jt * 64;
        const bool active = (j0 <= q0 + w * 16 + 15);
        if (active) {
            const uint32_t kb = kvbase + (jt & 1) * KVSTG_B;
            const bool need_mask = (j0 + 63 > q0 + w * 16);

            float S[8][4];
            #pragma unroll
            for (int nt = 0; nt < 8; ++nt)
                #pragma unroll
                for (int i = 0; i < 4; ++i) S[nt][i] = 0.f;

            #pragma unroll
            for (int ks = 0; ks < 4; ++ks) {
                const int brow = ((lane >> 4) & 1) * 8 + (lane & 7);
                const int bcolb = ks * 32 + ((lane >> 3) & 1) * 16;
                #pragma unroll
                for (int p = 0; p < 4; ++p) {
                    const uint32_t off = (uint32_t)(p * 16 + brow) * AT_ROWB + bcolb;
                    uint32_t kh[4];
                    ldsm4(kh, kb + off);
                    mma16816(S[2 * p],     qhi[ks], kh[0], kh[1]);
                    mma16816(S[2 * p + 1], qhi[ks], kh[2], kh[3]);
                    mma16816(S[2 * p],     qlo[ks], kh[0], kh[1]);
                    mma16816(S[2 * p + 1], qlo[ks], kh[2], kh[3]);
                }
            }

            float mx0 = -1e30f, mx1 = -1e30f;
            #pragma unroll
            for (int nt = 0; nt < 8; ++nt) {
                const int kgb = j0 + nt * 8 + (lane & 3) * 2;
                #pragma unroll
                for (int c = 0; c < 4; ++c) {
                    float v = S[nt][c] * SOFTMAX_SCALE;
                    if (need_mask) {
                        const int kg = kgb + (c & 1);
                        const int qg = qg0 + (c >> 1) * 8;
                        if (kg > qg) v = -1e30f;
                    }
                    S[nt][c] = v;
                }
                mx0 = fmaxf(mx0, fmaxf(S[nt][0], S[nt][1]));
                mx1 = fmaxf(mx1, fmaxf(S[nt][2], S[nt][3]));
            }
            mx0 = fmaxf(mx0, __shfl_xor_sync(0xffffffffu, mx0, 1));
            mx0 = fmaxf(mx0, __shfl_xor_sync(0xffffffffu, mx0, 2));
            mx1 = fmaxf(mx1, __shfl_xor_sync(0xffffffffu, mx1, 1));
            mx1 = fmaxf(mx1, __shfl_xor_sync(0xffffffffu, mx1, 2));
            const float mn0 = fmaxf(m0, mx0);
            const float mn1 = fmaxf(m1, mx1);
            const float c0 = __expf(m0 - mn0);
            const float c1 = __expf(m1 - mn1);
            float rs0 = 0.f, rs1 = 0.f;
            #pragma unroll
            for (int nt = 0; nt < 8; ++nt) {
                float p0 = __expf(S[nt][0] - mn0);
                float p1 = __expf(S[nt][1] - mn0);
                float p2 = __expf(S[nt][2] - mn1);
                float p3 = __expf(S[nt][3] - mn1);
                S[nt][0] = p0; S[nt][1] = p1; S[nt][2] = p2; S[nt][3] = p3;
                rs0 += p0 + p1;
                rs1 += p2 + p3;
            }
            rs0 += __shfl_xor_sync(0xffffffffu, rs0, 1);
            rs0 += __shfl_xor_sync(0xffffffffu, rs0, 2);
            rs1 += __shfl_xor_sync(0xffffffffu, rs1, 1);
            rs1 += __shfl_xor_sync(0xffffffffu, rs1, 2);
            l0 = l0 * c0 + rs0;
            l1 = l1 * c1 + rs1;
            #pragma unroll
            for (int nt = 0; nt < 8; ++nt) {
                O[nt][0] *= c0; O[nt][1] *= c0;
                O[nt][2] *= c1; O[nt][3] *= c1;
            }
            m0 = mn0; m1 = mn1;

            #pragma unroll
            for (int ks = 0; ks < 4; ++ks) {
                uint32_t aPhi[4], aPlo[4];
                pack_hl(S[2 * ks][0],     S[2 * ks][1],     aPhi[0], aPlo[0]);
                pack_hl(S[2 * ks][2],     S[2 * ks][3],     aPhi[1], aPlo[1]);
                pack_hl(S[2 * ks + 1][0], S[2 * ks + 1][1], aPhi[2], aPlo[2]);
                pack_hl(S[2 * ks + 1][2], S[2 * ks + 1][3], aPhi[3], aPlo[3]);
                const int mI = lane >> 3;
                const int r = lane & 7;
                #pragma unroll
                for (int p = 0; p < 4; ++p) {
                    const uint32_t off = (uint32_t)(ks * 16 + (mI & 1) * 8 + r) * AT_ROWB
                                       + p * 32 + (mI >> 1) * 16;
                    uint32_t vh[4];
                    ldsm4t(vh, kb + KTILE_B + off);
                    mma16816(O[2 * p],     aPhi, vh[0], vh[1]);
                    mma16816(O[2 * p + 1], aPhi, vh[2], vh[3]);
                    mma16816(O[2 * p],     aPlo, vh[0], vh[1]);
                    mma16816(O[2 * p + 1], aPlo, vh[2], vh[3]);
                }
            }
        }
        __syncthreads();
        if (jt + 2 < ntiles) issueKV(jt + 2, jt & 1);
    }

    const float inv0 = 1.f / l0;
    const float inv1 = 1.f / l1;
    const size_t r0 = rowbase + q0 + w * 16 + (lane >> 2);
    #pragma unroll
    for (int nt = 0; nt < 8; ++nt) {
        const int col = (int)hoff + nt * 8 + (lane & 3) * 2;
        uint32_t h0, l0p, h1, l1p;
        pack_hl(O[nt][0] * inv0, O[nt][1] * inv0, h0, l0p);
        pack_hl(O[nt][2] * inv1, O[nt][3] * inv1, h1, l1p);
        *(uint32_t*)&g_chi[r0 * DMODEL + col] = h0;
        *(uint32_t*)&g_clo[r0 * DMODEL + col] = l0p;
        *(uint32_t*)&g_chi[(r0 + 8) * DMODEL + col] = h1;
        *(uint32_t*)&g_clo[(r0 + 8) * DMODEL + col] = l1p;
    }
}

// ---------------------------------------------------------------------------
// Launch
// ---------------------------------------------------------------------------
extern "C" void kernel_launch(void* const* d_in, const int* in_sizes, int n_in,
                              void* d_out, int out_size)
{
    const float* x  = (const float*)d_in[0];
    const float* Wq = (const float*)d_in[1];
    const float* Wk = (const float*)d_in[2];
    const float* Wv = (const float*)d_in[3];
    const float* Wo = (const float*)d_in[4];
    const float* bo = (const float*)d_in[5];
    float* out = (float*)d_out;

    __half *xhi, *xlo, *wtqkv, *wto, *chi, *clo;
    cudaGetSymbolAddress((void**)&xhi, g_xhi);
    cudaGetSymbolAddress((void**)&xlo, g_xlo);
    cudaGetSymbolAddress((void**)&wtqkv, g_wtqkv);
    cudaGetSymbolAddress((void**)&wto, g_wto);
    cudaGetSymbolAddress((void**)&chi, g_chi);
    cudaGetSymbolAddress((void**)&clo, g_clo);

    cudaFuncSetAttribute(gemm_mma_kernel,
                         cudaFuncAttributeMaxDynamicSharedMemorySize, GEMM_SMEM);
    cudaFuncSetAttribute(attn_tc_kernel,
                         cudaFuncAttributeMaxDynamicSharedMemorySize, ATTN_SMEM);

    const int n4 = MROWS * DMODEL / 4;
    split_kernel<<<(n4 + 255) / 256, 256>>>(x, n4);

    dim3 ts_grid(DMODEL / 32, DMODEL / 32, 4);
    tsplit4_kernel<<<ts_grid, dim3(32, 8)>>>(Wq, Wk, Wv, Wo);

    // fused QKV projection
    dim3 gq(3 * DMODEL / 128, MROWS / 128);   // (24, 64)
    gemm_mma_kernel<<<gq, 256, GEMM_SMEM>>>(xhi, xlo, wtqkv, nullptr, nullptr, 1);

    // causal flash attention
    dim3 attn_grid(SEQ / 128, BATCH * NHEAD);
    attn_tc_kernel<<<attn_grid, 256, ATTN_SMEM>>>();

    // output projection + bias
    dim3 go(DMODEL / 128, MROWS / 128);       // (8, 64)
    gemm_mma_kernel<<<go, 256, GEMM_SMEM>>>(chi, clo, wto, out, bo, 0);
}

// round 6
// speedup vs baseline: 10.3247x; 1.6638x over previous
#include <cuda_runtime.h>
#include <cuda_fp16.h>
#include <cstdint>

// Problem constants
#define BATCH 4
#define SEQ   2048
#define DMODEL 1024
#define NHEAD 16
#define HDIM  64
#define MROWS (BATCH * SEQ)          // 8192
#define SOFTMAX_SCALE 0.125f         // 1/sqrt(64)

// ---------------------------------------------------------------------------
// Scratch (static device globals)
// ---------------------------------------------------------------------------
__device__ __half g_xh[MROWS * DMODEL];
__device__ __half g_wtqkv[3 * DMODEL * DMODEL];   // Wq^T;Wk^T;Wv^T fp16
__device__ __half g_wto[DMODEL * DMODEL];         // Wo^T fp16
__device__ __half g_qh[MROWS * DMODEL];
__device__ __half g_kh[MROWS * DMODEL];
__device__ __half g_vh[MROWS * DMODEL];
__device__ __half g_ch[MROWS * DMODEL];

// ---------------------------------------------------------------------------
// PTX helpers (sm_80+ only)
// ---------------------------------------------------------------------------
__device__ __forceinline__ uint32_t smem_u32(const void* p) {
    uint32_t a;
    asm("{ .reg .u64 t; cvta.to.shared.u64 t, %1; cvt.u32.u64 %0, t; }"
        : "=r"(a) : "l"(p));
    return a;
}
__device__ __forceinline__ void cp_async16(uint32_t dst, const void* src) {
    asm volatile("cp.async.cg.shared.global [%0], [%1], 16;"
                 :: "r"(dst), "l"(__cvta_generic_to_global(src)) : "memory");
}
__device__ __forceinline__ void cp_commit() {
    asm volatile("cp.async.commit_group;" ::: "memory");
}
__device__ __forceinline__ void ldsm4(uint32_t (&r)[4], uint32_t addr) {
    asm volatile("ldmatrix.sync.aligned.m8n8.x4.shared.b16 {%0,%1,%2,%3}, [%4];"
                 : "=r"(r[0]), "=r"(r[1]), "=r"(r[2]), "=r"(r[3]) : "r"(addr));
}
__device__ __forceinline__ void ldsm4t(uint32_t (&r)[4], uint32_t addr) {
    asm volatile("ldmatrix.sync.aligned.m8n8.x4.trans.shared.b16 {%0,%1,%2,%3}, [%4];"
                 : "=r"(r[0]), "=r"(r[1]), "=r"(r[2]), "=r"(r[3]) : "r"(addr));
}
__device__ __forceinline__ void mma16816(float (&d)[4], const uint32_t (&a)[4],
                                         uint32_t b0, uint32_t b1) {
    asm volatile(
        "mma.sync.aligned.m16n8k16.row.col.f32.f16.f16.f32 "
        "{%0,%1,%2,%3}, {%4,%5,%6,%7}, {%8,%9}, {%0,%1,%2,%3};"
        : "+f"(d[0]), "+f"(d[1]), "+f"(d[2]), "+f"(d[3])
        : "r"(a[0]), "r"(a[1]), "r"(a[2]), "r"(a[3]), "r"(b0), "r"(b1));
}
__device__ __forceinline__ uint32_t pack_h(float a, float b) {
    __half2 h = __floats2half2_rn(a, b);
    return *(uint32_t*)&h;
}

// ---------------------------------------------------------------------------
// Convert fp32 x -> fp16
// ---------------------------------------------------------------------------
__global__ __launch_bounds__(256)
void convert_kernel(const float* __restrict__ in, int n4)
{
    int i = blockIdx.x * blockDim.x + threadIdx.x;
    if (i >= n4) return;
    float4 v = *(const float4*)(in + (size_t)i * 4);
    uint2 hv = { pack_h(v.x, v.y), pack_h(v.z, v.w) };
    *(uint2*)&g_xh[(size_t)i * 4] = hv;
}

// ---------------------------------------------------------------------------
// Transpose all 4 weights: W[K][N] fp32 -> WT[N][K] fp16
// ---------------------------------------------------------------------------
__global__ __launch_bounds__(256)
void tsplit4_kernel(const float* __restrict__ W0, const float* __restrict__ W1,
                    const float* __restrict__ W2, const float* __restrict__ W3)
{
    __shared__ float t[32][33];
    const int z = blockIdx.z;
    const float* W = (z == 0) ? W0 : (z == 1) ? W1 : (z == 2) ? W2 : W3;
    __half* dst = (z < 3) ? (g_wtqkv + (size_t)z * DMODEL * DMODEL) : g_wto;

    const int n0 = blockIdx.x * 32;
    const int k0 = blockIdx.y * 32;
    const int tx = threadIdx.x;
    const int ty = threadIdx.y;
    #pragma unroll
    for (int i = 0; i < 4; ++i)
        t[ty + 8 * i][tx] = W[(size_t)(k0 + ty + 8 * i) * DMODEL + n0 + tx];
    __syncthreads();
    #pragma unroll
    for (int i = 0; i < 4; ++i)
        dst[(size_t)(n0 + ty + 8 * i) * DMODEL + k0 + tx] = __float2half_rn(t[tx][ty + 8 * i]);
}

// ---------------------------------------------------------------------------
// Single-pass fp16 GEMM: out = A[M,K] @ BT[N,K]^T
// 128x128 tile, BK=32, 8 warps (2m x 4n), 2-stage cp.async pipeline.
// qkv_mode 1: grid.x = 24 -> g_qh / g_kh / g_vh by n-block.
// qkv_mode 0: fp32 out + bias.
// ---------------------------------------------------------------------------
#define GBK    32
#define ROWB   80
#define TILE_B (128 * ROWB)
#define STAGE_B (2 * TILE_B)            // A, B
#define NCH    (DMODEL / GBK)
#define GEMM_SMEM (2 * STAGE_B)         // 40960

__global__ __launch_bounds__(256, 2)
void gemm_mma_kernel(const __half* __restrict__ Ah, const __half* __restrict__ Bh,
                     float* __restrict__ C, const float* __restrict__ bias, int qkv_mode)
{
    extern __shared__ char sm[];
    const uint32_t sbase = smem_u32(sm);

    const int tid = threadIdx.x;
    const int wid = tid >> 5;
    const int lane = tid & 31;
    const int warp_m = wid & 1;
    const int warp_n = wid >> 1;
    const int n0 = blockIdx.x * 128;
    const int m0 = blockIdx.y * 128;

    float acc[4][4][4];
    #pragma unroll
    for (int mt = 0; mt < 4; ++mt)
        #pragma unroll
        for (int nt = 0; nt < 4; ++nt)
            #pragma unroll
            for (int i = 0; i < 4; ++i) acc[mt][nt][i] = 0.f;

    auto issue = [&](int c) {
        const uint32_t dstb = sbase + (c & 1) * STAGE_B;
        const int k0 = c * GBK;
        #pragma unroll
        for (int t = 0; t < 4; ++t) {
            const int idx = t * 256 + tid;        // 0..1023
            const int tile = idx >> 9;            // 0 A, 1 B
            const int row = (idx >> 2) & 127;
            const int seg = idx & 3;
            const __half* src = (tile == 0) ? Ah + (size_t)(m0 + row) * DMODEL
                                            : Bh + (size_t)(n0 + row) * DMODEL;
            cp_async16(dstb + tile * TILE_B + row * ROWB + seg * 16, src + k0 + seg * 8);
        }
        cp_commit();
    };

    issue(0);

    for (int c = 0; c < NCH; ++c) {
        if (c + 1 < NCH) {
            issue(c + 1);
            asm volatile("cp.async.wait_group 1;" ::: "memory");
        } else {
            asm volatile("cp.async.wait_group 0;" ::: "memory");
        }
        __syncthreads();

        const uint32_t sb = sbase + (c & 1) * STAGE_B;

        #pragma unroll
        for (int ks = 0; ks < 2; ++ks) {
            uint32_t ah[4][4];
            const int arow_base = warp_m * 64 + (lane & 15);
            const int acolb = ks * 32 + ((lane >> 4) << 4);
            #pragma unroll
            for (int mt = 0; mt < 4; ++mt) {
                const uint32_t off = (uint32_t)(arow_base + mt * 16) * ROWB + acolb;
                ldsm4(ah[mt], sb + off);
            }
            uint32_t bh[4][2];
            const int brow_base = warp_n * 32 + ((lane >> 4) & 1) * 8 + (lane & 7);
            const int bcolb = ks * 32 + ((lane >> 3) & 1) * 16;
            #pragma unroll
            for (int p = 0; p < 2; ++p) {
                const uint32_t off = (uint32_t)(brow_base + p * 16) * ROWB + bcolb;
                uint32_t r4[4];
                ldsm4(r4, sb + TILE_B + off);
                bh[2 * p][0] = r4[0]; bh[2 * p][1] = r4[1];
                bh[2 * p + 1][0] = r4[2]; bh[2 * p + 1][1] = r4[3];
            }
            #pragma unroll
            for (int mt = 0; mt < 4; ++mt)
                #pragma unroll
                for (int nt = 0; nt < 4; ++nt)
                    mma16816(acc[mt][nt], ah[mt], bh[nt][0], bh[nt][1]);
        }
        __syncthreads();
    }

    const int g = lane >> 2;
    const int t4 = lane & 3;
    if (qkv_mode) {
        const int mat = n0 >> 10;                 // 0 Q, 1 K, 2 V
        const int nloc = n0 & 1023;
        __half* dst = (mat == 0) ? g_qh : (mat == 1) ? g_kh : g_vh;
        #pragma unroll
        for (int mt = 0; mt < 4; ++mt)
            #pragma unroll
            for (int nt = 0; nt < 4; ++nt) {
                const int col = nloc + warp_n * 32 + nt * 8 + t4 * 2;
                const size_t r0 = (size_t)(m0 + warp_m * 64 + mt * 16 + g);
                *(uint32_t*)&dst[r0 * DMODEL + col] = pack_h(acc[mt][nt][0], acc[mt][nt][1]);
                *(uint32_t*)&dst[(r0 + 8) * DMODEL + col] = pack_h(acc[mt][nt][2], acc[mt][nt][3]);
            }
    } else {
        #pragma unroll
        for (int mt = 0; mt < 4; ++mt)
            #pragma unroll
            for (int nt = 0; nt < 4; ++nt) {
                const int col = n0 + warp_n * 32 + nt * 8 + t4 * 2;
                const size_t r0 = (size_t)(m0 + warp_m * 64 + mt * 16 + g);
                float2 v0 = { acc[mt][nt][0], acc[mt][nt][1] };
                float2 v1 = { acc[mt][nt][2], acc[mt][nt][3] };
                const float b0 = bias[col], b1 = bias[col + 1];
                v0.x += b0; v0.y += b1;
                v1.x += b0; v1.y += b1;
                *(float2*)&C[r0 * DMODEL + col] = v0;
                *(float2*)&C[(r0 + 8) * DMODEL + col] = v1;
            }
    }
}

// ---------------------------------------------------------------------------
// Tensor-core flash attention (causal), fp16 single-pass, fp32 softmax.
// grid (SEQ/128, B*H); 256 threads (8 warps x 16 q-rows each).
// ---------------------------------------------------------------------------
#define AT_ROWB  144                        // 64 fp16 = 128B + 16B pad
#define QTILE_B  (128 * AT_ROWB)            // 18432
#define KTILE_B  (64 * AT_ROWB)             // 9216
#define KVSTG_B  (2 * KTILE_B)              // 18432 (K + V)
#define ATTN_SMEM (QTILE_B + 2 * KVSTG_B)   // 55296

__global__ __launch_bounds__(256, 2)
void attn_tc_kernel()
{
    extern __shared__ char sm[];
    const uint32_t sbase = smem_u32(sm);
    const uint32_t kvbase = sbase + QTILE_B;

    const int tid = threadIdx.x;
    const int w = tid >> 5;
    const int lane = tid & 31;
    const int qt = blockIdx.x;
    const int bh = blockIdx.y;
    const int b = bh >> 4;
    const int h = bh & 15;
    const int q0 = qt * 128;
    const size_t rowbase = (size_t)b * SEQ;
    const size_t hoff = (size_t)h * HDIM;

    const int ntiles = qt * 2 + 2;

    auto issueQ = [&]() {
        #pragma unroll
        for (int t = 0; t < 4; ++t) {
            const int idx = t * 256 + tid;       // 0..1023
            const int row = idx >> 3;
            const int seg = idx & 7;
            const __half* src = g_qh + (rowbase + q0 + row) * DMODEL + hoff + seg * 8;
            cp_async16(sbase + row * AT_ROWB + seg * 16, src);
        }
    };
    auto issueKV = [&](int jt, int stage) {
        const int j0 = jt * 64;
        #pragma unroll
        for (int t = 0; t < 4; ++t) {
            const int idx = t * 256 + tid;       // 0..1023
            const int ten = idx >> 9;            // 0 K, 1 V
            const int row = (idx >> 3) & 63;
            const int seg = idx & 7;
            const __half* src = (ten == 0 ? g_kh : g_vh) +
                (rowbase + j0 + row) * DMODEL + hoff + seg * 8;
            cp_async16(kvbase + stage * KVSTG_B + ten * KTILE_B + row * AT_ROWB + seg * 16, src);
        }
        cp_commit();
    };

    issueQ();
    issueKV(0, 0);
    if (ntiles > 1) issueKV(1, 1);

    float O[8][4];
    #pragma unroll
    for (int nt = 0; nt < 8; ++nt)
        #pragma unroll
        for (int i = 0; i < 4; ++i) O[nt][i] = 0.f;
    float m0 = -1e30f, m1 = -1e30f, l0 = 0.f, l1 = 0.f;

    uint32_t qh[4][4];
    const int qg0 = q0 + w * 16 + (lane >> 2);

    for (int jt = 0; jt < ntiles; ++jt) {
        if (jt + 1 < ntiles)
            asm volatile("cp.async.wait_group 1;" ::: "memory");
        else
            asm volatile("cp.async.wait_group 0;" ::: "memory");
        __syncthreads();

        if (jt == 0) {
            const int arow = w * 16 + (lane & 15);
            #pragma unroll
            for (int ks = 0; ks < 4; ++ks) {
                const uint32_t off = (uint32_t)arow * AT_ROWB + ks * 32 + ((lane >> 4) << 4);
                ldsm4(qh[ks], sbase + off);
            }
        }

        const int j0 = jt * 64;
        const bool active = (j0 <= q0 + w * 16 + 15);
        if (active) {
            const uint32_t kb = kvbase + (jt & 1) * KVSTG_B;
            const bool need_mask = (j0 + 63 > q0 + w * 16);

            float S[8][4];
            #pragma unroll
            for (int nt = 0; nt < 8; ++nt)
                #pragma unroll
                for (int i = 0; i < 4; ++i) S[nt][i] = 0.f;

            #pragma unroll
            for (int ks = 0; ks < 4; ++ks) {
                const int brow = ((lane >> 4) & 1) * 8 + (lane & 7);
                const int bcolb = ks * 32 + ((lane >> 3) & 1) * 16;
                #pragma unroll
                for (int p = 0; p < 4; ++p) {
                    const uint32_t off = (uint32_t)(p * 16 + brow) * AT_ROWB + bcolb;
                    uint32_t kh[4];
                    ldsm4(kh, kb + off);
                    mma16816(S[2 * p],     qh[ks], kh[0], kh[1]);
                    mma16816(S[2 * p + 1], qh[ks], kh[2], kh[3]);
                }
            }

            float mx0 = -1e30f, mx1 = -1e30f;
            #pragma unroll
            for (int nt = 0; nt < 8; ++nt) {
                const int kgb = j0 + nt * 8 + (lane & 3) * 2;
                #pragma unroll
                for (int c = 0; c < 4; ++c) {
                    float v = S[nt][c] * SOFTMAX_SCALE;
                    if (need_mask) {
                        const int kg = kgb + (c & 1);
                        const int qg = qg0 + (c >> 1) * 8;
                        if (kg > qg) v = -1e30f;
                    }
                    S[nt][c] = v;
                }
                mx0 = fmaxf(mx0, fmaxf(S[nt][0], S[nt][1]));
                mx1 = fmaxf(mx1, fmaxf(S[nt][2], S[nt][3]));
            }
            mx0 = fmaxf(mx0, __shfl_xor_sync(0xffffffffu, mx0, 1));
            mx0 = fmaxf(mx0, __shfl_xor_sync(0xffffffffu, mx0, 2));
            mx1 = fmaxf(mx1, __shfl_xor_sync(0xffffffffu, mx1, 1));
            mx1 = fmaxf(mx1, __shfl_xor_sync(0xffffffffu, mx1, 2));
            const float mn0 = fmaxf(m0, mx0);
            const float mn1 = fmaxf(m1, mx1);
            const float c0 = __expf(m0 - mn0);
            const float c1 = __expf(m1 - mn1);
            float rs0 = 0.f, rs1 = 0.f;
            #pragma unroll
            for (int nt = 0; nt < 8; ++nt) {
                float p0 = __expf(S[nt][0] - mn0);
                float p1 = __expf(S[nt][1] - mn0);
                float p2 = __expf(S[nt][2] - mn1);
                float p3 = __expf(S[nt][3] - mn1);
                S[nt][0] = p0; S[nt][1] = p1; S[nt][2] = p2; S[nt][3] = p3;
                rs0 += p0 + p1;
                rs1 += p2 + p3;
            }
            rs0 += __shfl_xor_sync(0xffffffffu, rs0, 1);
            rs0 += __shfl_xor_sync(0xffffffffu, rs0, 2);
            rs1 += __shfl_xor_sync(0xffffffffu, rs1, 1);
            rs1 += __shfl_xor_sync(0xffffffffu, rs1, 2);
            l0 = l0 * c0 + rs0;
            l1 = l1 * c1 + rs1;
            #pragma unroll
            for (int nt = 0; nt < 8; ++nt) {
                O[nt][0] *= c0; O[nt][1] *= c0;
                O[nt][2] *= c1; O[nt][3] *= c1;
            }
            m0 = mn0; m1 = mn1;

            #pragma unroll
            for (int ks = 0; ks < 4; ++ks) {
                uint32_t aP[4];
                aP[0] = pack_h(S[2 * ks][0],     S[2 * ks][1]);
                aP[1] = pack_h(S[2 * ks][2],     S[2 * ks][3]);
                aP[2] = pack_h(S[2 * ks + 1][0], S[2 * ks + 1][1]);
                aP[3] = pack_h(S[2 * ks + 1][2], S[2 * ks + 1][3]);
                const int mI = lane >> 3;
                const int r = lane & 7;
                #pragma unroll
                for (int p = 0; p < 4; ++p) {
                    const uint32_t off = (uint32_t)(ks * 16 + (mI & 1) * 8 + r) * AT_ROWB
                                       + p * 32 + (mI >> 1) * 16;
                    uint32_t vh[4];
                    ldsm4t(vh, kb + KTILE_B + off);
                    mma16816(O[2 * p],     aP, vh[0], vh[1]);
                    mma16816(O[2 * p + 1], aP, vh[2], vh[3]);
                }
            }
        }
        __syncthreads();
        if (jt + 2 < ntiles) issueKV(jt + 2, jt & 1);
    }

    const float inv0 = 1.f / l0;
    const float inv1 = 1.f / l1;
    const size_t r0 = rowbase + q0 + w * 16 + (lane >> 2);
    #pragma unroll
    for (int nt = 0; nt < 8; ++nt) {
        const int col = (int)hoff + nt * 8 + (lane & 3) * 2;
        *(uint32_t*)&g_ch[r0 * DMODEL + col] = pack_h(O[nt][0] * inv0, O[nt][1] * inv0);
        *(uint32_t*)&g_ch[(r0 + 8) * DMODEL + col] = pack_h(O[nt][2] * inv1, O[nt][3] * inv1);
    }
}

// ---------------------------------------------------------------------------
// Launch
// ---------------------------------------------------------------------------
extern "C" void kernel_launch(void* const* d_in, const int* in_sizes, int n_in,
                              void* d_out, int out_size)
{
    const float* x  = (const float*)d_in[0];
    const float* Wq = (const float*)d_in[1];
    const float* Wk = (const float*)d_in[2];
    const float* Wv = (const float*)d_in[3];
    const float* Wo = (const float*)d_in[4];
    const float* bo = (const float*)d_in[5];
    float* out = (float*)d_out;

    __half *xh, *wtqkv, *wto, *ch;
    cudaGetSymbolAddress((void**)&xh, g_xh);
    cudaGetSymbolAddress((void**)&wtqkv, g_wtqkv);
    cudaGetSymbolAddress((void**)&wto, g_wto);
    cudaGetSymbolAddress((void**)&ch, g_ch);

    cudaFuncSetAttribute(gemm_mma_kernel,
                         cudaFuncAttributeMaxDynamicSharedMemorySize, GEMM_SMEM);
    cudaFuncSetAttribute(attn_tc_kernel,
                         cudaFuncAttributeMaxDynamicSharedMemorySize, ATTN_SMEM);

    const int n4 = MROWS * DMODEL / 4;
    convert_kernel<<<(n4 + 255) / 256, 256>>>(x, n4);

    dim3 ts_grid(DMODEL / 32, DMODEL / 32, 4);
    tsplit4_kernel<<<ts_grid, dim3(32, 8)>>>(Wq, Wk, Wv, Wo);

    // fused QKV projection
    dim3 gq(3 * DMODEL / 128, MROWS / 128);   // (24, 64)
    gemm_mma_kernel<<<gq, 256, GEMM_SMEM>>>(xh, wtqkv, nullptr, nullptr, 1);

    // causal flash attention
    dim3 attn_grid(SEQ / 128, BATCH * NHEAD);
    attn_tc_kernel<<<attn_grid, 256, ATTN_SMEM>>>();

    // output projection + bias
    dim3 go(DMODEL / 128, MROWS / 128);       // (8, 64)
    gemm_mma_kernel<<<go, 256, GEMM_SMEM>>>(ch, wto, out, bo, 0);
}

// round 7
// speedup vs baseline: 10.9252x; 1.0582x over previous
#include <cuda_runtime.h>
#include <cuda_fp16.h>
#include <cstdint>

// Problem constants
#define BATCH 4
#define SEQ   2048
#define DMODEL 1024
#define NHEAD 16
#define HDIM  64
#define MROWS (BATCH * SEQ)          // 8192
// 0.125 * log2(e): folded into Q so logits are in log2 domain
#define QSCALE 0.18033688f

// ---------------------------------------------------------------------------
// Scratch (static device globals)
// ---------------------------------------------------------------------------
__device__ __half g_xh[MROWS * DMODEL];
__device__ __half g_wtqkv[3 * DMODEL * DMODEL];   // Wq^T;Wk^T;Wv^T fp16
__device__ __half g_wto[DMODEL * DMODEL];         // Wo^T fp16
__device__ __half g_qh[MROWS * DMODEL];           // pre-scaled by QSCALE
__device__ __half g_kh[MROWS * DMODEL];
__device__ __half g_vh[MROWS * DMODEL];
__device__ __half g_ch[MROWS * DMODEL];

// ---------------------------------------------------------------------------
// PTX helpers (sm_80+ only)
// ---------------------------------------------------------------------------
__device__ __forceinline__ uint32_t smem_u32(const void* p) {
    uint32_t a;
    asm("{ .reg .u64 t; cvta.to.shared.u64 t, %1; cvt.u32.u64 %0, t; }"
        : "=r"(a) : "l"(p));
    return a;
}
__device__ __forceinline__ void cp_async16(uint32_t dst, const void* src) {
    asm volatile("cp.async.cg.shared.global [%0], [%1], 16;"
                 :: "r"(dst), "l"(__cvta_generic_to_global(src)) : "memory");
}
__device__ __forceinline__ void cp_commit() {
    asm volatile("cp.async.commit_group;" ::: "memory");
}
__device__ __forceinline__ void ldsm4(uint32_t (&r)[4], uint32_t addr) {
    asm volatile("ldmatrix.sync.aligned.m8n8.x4.shared.b16 {%0,%1,%2,%3}, [%4];"
                 : "=r"(r[0]), "=r"(r[1]), "=r"(r[2]), "=r"(r[3]) : "r"(addr));
}
__device__ __forceinline__ void ldsm4t(uint32_t (&r)[4], uint32_t addr) {
    asm volatile("ldmatrix.sync.aligned.m8n8.x4.trans.shared.b16 {%0,%1,%2,%3}, [%4];"
                 : "=r"(r[0]), "=r"(r[1]), "=r"(r[2]), "=r"(r[3]) : "r"(addr));
}
__device__ __forceinline__ void mma16816(float (&d)[4], const uint32_t (&a)[4],
                                         uint32_t b0, uint32_t b1) {
    asm volatile(
        "mma.sync.aligned.m16n8k16.row.col.f32.f16.f16.f32 "
        "{%0,%1,%2,%3}, {%4,%5,%6,%7}, {%8,%9}, {%0,%1,%2,%3};"
        : "+f"(d[0]), "+f"(d[1]), "+f"(d[2]), "+f"(d[3])
        : "r"(a[0]), "r"(a[1]), "r"(a[2]), "r"(a[3]), "r"(b0), "r"(b1));
}
__device__ __forceinline__ uint32_t pack_h(float a, float b) {
    __half2 h = __floats2half2_rn(a, b);
    return *(uint32_t*)&h;
}
__device__ __forceinline__ float ex2(float x) {
    float y;
    asm("ex2.approx.ftz.f32 %0, %1;" : "=f"(y) : "f"(x));
    return y;
}

// ---------------------------------------------------------------------------
// Convert fp32 x -> fp16
// ---------------------------------------------------------------------------
__global__ __launch_bounds__(256)
void convert_kernel(const float* __restrict__ in, int n4)
{
    int i = blockIdx.x * blockDim.x + threadIdx.x;
    if (i >= n4) return;
    float4 v = *(const float4*)(in + (size_t)i * 4);
    uint2 hv = { pack_h(v.x, v.y), pack_h(v.z, v.w) };
    *(uint2*)&g_xh[(size_t)i * 4] = hv;
}

// ---------------------------------------------------------------------------
// Transpose all 4 weights: W[K][N] fp32 -> WT[N][K] fp16
// ---------------------------------------------------------------------------
__global__ __launch_bounds__(256)
void tsplit4_kernel(const float* __restrict__ W0, const float* __restrict__ W1,
                    const float* __restrict__ W2, const float* __restrict__ W3)
{
    __shared__ float t[32][33];
    const int z = blockIdx.z;
    const float* W = (z == 0) ? W0 : (z == 1) ? W1 : (z == 2) ? W2 : W3;
    __half* dst = (z < 3) ? (g_wtqkv + (size_t)z * DMODEL * DMODEL) : g_wto;

    const int n0 = blockIdx.x * 32;
    const int k0 = blockIdx.y * 32;
    const int tx = threadIdx.x;
    const int ty = threadIdx.y;
    #pragma unroll
    for (int i = 0; i < 4; ++i)
        t[ty + 8 * i][tx] = W[(size_t)(k0 + ty + 8 * i) * DMODEL + n0 + tx];
    __syncthreads();
    #pragma unroll
    for (int i = 0; i < 4; ++i)
        dst[(size_t)(n0 + ty + 8 * i) * DMODEL + k0 + tx] = __float2half_rn(t[tx][ty + 8 * i]);
}

// ---------------------------------------------------------------------------
// Single-pass fp16 GEMM: out = A[M,K] @ BT[N,K]^T
// 128x128 tile, BK=32, 8 warps (2m x 4n), 2-stage cp.async pipeline.
// qkv_mode 1: grid.x = 24 -> g_qh (scaled by QSCALE) / g_kh / g_vh.
// qkv_mode 0: fp32 out + bias.
// ---------------------------------------------------------------------------
#define GBK    32
#define ROWB   80
#define TILE_B (128 * ROWB)
#define STAGE_B (2 * TILE_B)
#define NCH    (DMODEL / GBK)
#define GEMM_SMEM (2 * STAGE_B)         // 40960

__global__ __launch_bounds__(256, 2)
void gemm_mma_kernel(const __half* __restrict__ Ah, const __half* __restrict__ Bh,
                     float* __restrict__ C, const float* __restrict__ bias, int qkv_mode)
{
    extern __shared__ char sm[];
    const uint32_t sbase = smem_u32(sm);

    const int tid = threadIdx.x;
    const int wid = tid >> 5;
    const int lane = tid & 31;
    const int warp_m = wid & 1;
    const int warp_n = wid >> 1;
    const int n0 = blockIdx.x * 128;
    const int m0 = blockIdx.y * 128;

    float acc[4][4][4];
    #pragma unroll
    for (int mt = 0; mt < 4; ++mt)
        #pragma unroll
        for (int nt = 0; nt < 4; ++nt)
            #pragma unroll
            for (int i = 0; i < 4; ++i) acc[mt][nt][i] = 0.f;

    auto issue = [&](int c) {
        const uint32_t dstb = sbase + (c & 1) * STAGE_B;
        const int k0 = c * GBK;
        #pragma unroll
        for (int t = 0; t < 4; ++t) {
            const int idx = t * 256 + tid;        // 0..1023
            const int tile = idx >> 9;            // 0 A, 1 B
            const int row = (idx >> 2) & 127;
            const int seg = idx & 3;
            const __half* src = (tile == 0) ? Ah + (size_t)(m0 + row) * DMODEL
                                            : Bh + (size_t)(n0 + row) * DMODEL;
            cp_async16(dstb + tile * TILE_B + row * ROWB + seg * 16, src + k0 + seg * 8);
        }
        cp_commit();
    };

    issue(0);

    for (int c = 0; c < NCH; ++c) {
        if (c + 1 < NCH) {
            issue(c + 1);
            asm volatile("cp.async.wait_group 1;" ::: "memory");
        } else {
            asm volatile("cp.async.wait_group 0;" ::: "memory");
        }
        __syncthreads();

        const uint32_t sb = sbase + (c & 1) * STAGE_B;

        #pragma unroll
        for (int ks = 0; ks < 2; ++ks) {
            uint32_t ah[4][4];
            const int arow_base = warp_m * 64 + (lane & 15);
            const int acolb = ks * 32 + ((lane >> 4) << 4);
            #pragma unroll
            for (int mt = 0; mt < 4; ++mt) {
                const uint32_t off = (uint32_t)(arow_base + mt * 16) * ROWB + acolb;
                ldsm4(ah[mt], sb + off);
            }
            uint32_t bh[4][2];
            const int brow_base = warp_n * 32 + ((lane >> 4) & 1) * 8 + (lane & 7);
            const int bcolb = ks * 32 + ((lane >> 3) & 1) * 16;
            #pragma unroll
            for (int p = 0; p < 2; ++p) {
                const uint32_t off = (uint32_t)(brow_base + p * 16) * ROWB + bcolb;
                uint32_t r4[4];
                ldsm4(r4, sb + TILE_B + off);
                bh[2 * p][0] = r4[0]; bh[2 * p][1] = r4[1];
                bh[2 * p + 1][0] = r4[2]; bh[2 * p + 1][1] = r4[3];
            }
            #pragma unroll
            for (int mt = 0; mt < 4; ++mt)
                #pragma unroll
                for (int nt = 0; nt < 4; ++nt)
                    mma16816(acc[mt][nt], ah[mt], bh[nt][0], bh[nt][1]);
        }
        __syncthreads();
    }

    const int g = lane >> 2;
    const int t4 = lane & 3;
    if (qkv_mode) {
        const int mat = n0 >> 10;                 // 0 Q, 1 K, 2 V
        const int nloc = n0 & 1023;
        __half* dst = (mat == 0) ? g_qh : (mat == 1) ? g_kh : g_vh;
        const float s = (mat == 0) ? QSCALE : 1.0f;
        #pragma unroll
        for (int mt = 0; mt < 4; ++mt)
            #pragma unroll
            for (int nt = 0; nt < 4; ++nt) {
                const int col = nloc + warp_n * 32 + nt * 8 + t4 * 2;
                const size_t r0 = (size_t)(m0 + warp_m * 64 + mt * 16 + g);
                *(uint32_t*)&dst[r0 * DMODEL + col] =
                    pack_h(acc[mt][nt][0] * s, acc[mt][nt][1] * s);
                *(uint32_t*)&dst[(r0 + 8) * DMODEL + col] =
                    pack_h(acc[mt][nt][2] * s, acc[mt][nt][3] * s);
            }
    } else {
        #pragma unroll
        for (int mt = 0; mt < 4; ++mt)
            #pragma unroll
            for (int nt = 0; nt < 4; ++nt) {
                const int col = n0 + warp_n * 32 + nt * 8 + t4 * 2;
                const size_t r0 = (size_t)(m0 + warp_m * 64 + mt * 16 + g);
                float2 v0 = { acc[mt][nt][0], acc[mt][nt][1] };
                float2 v1 = { acc[mt][nt][2], acc[mt][nt][3] };
                const float b0 = bias[col], b1 = bias[col + 1];
                v0.x += b0; v0.y += b1;
                v1.x += b0; v1.y += b1;
                *(float2*)&C[r0 * DMODEL + col] = v0;
                *(float2*)&C[(r0 + 8) * DMODEL + col] = v1;
            }
    }
}

// ---------------------------------------------------------------------------
// Tensor-core flash attention (causal), fp16, log2-domain softmax (ex2).
// grid (SEQ/128, B*H); 256 threads (8 warps x 16 q-rows each).
// ---------------------------------------------------------------------------
#define AT_ROWB  144                        // 64 fp16 = 128B + 16B pad
#define QTILE_B  (128 * AT_ROWB)            // 18432
#define KTILE_B  (64 * AT_ROWB)             // 9216
#define KVSTG_B  (2 * KTILE_B)              // 18432 (K + V)
#define ATTN_SMEM (QTILE_B + 2 * KVSTG_B)   // 55296

__global__ __launch_bounds__(256, 2)
void attn_tc_kernel()
{
    extern __shared__ char sm[];
    const uint32_t sbase = smem_u32(sm);
    const uint32_t kvbase = sbase + QTILE_B;

    const int tid = threadIdx.x;
    const int w = tid >> 5;
    const int lane = tid & 31;
    const int qt = blockIdx.x;
    const int bh = blockIdx.y;
    const int b = bh >> 4;
    const int h = bh & 15;
    const int q0 = qt * 128;
    const size_t rowbase = (size_t)b * SEQ;
    const size_t hoff = (size_t)h * HDIM;

    const int ntiles = qt * 2 + 2;

    auto issueQ = [&]() {
        #pragma unroll
        for (int t = 0; t < 4; ++t) {
            const int idx = t * 256 + tid;
            const int row = idx >> 3;
            const int seg = idx & 7;
            const __half* src = g_qh + (rowbase + q0 + row) * DMODEL + hoff + seg * 8;
            cp_async16(sbase + row * AT_ROWB + seg * 16, src);
        }
    };
    auto issueKV = [&](int jt, int stage) {
        const int j0 = jt * 64;
        #pragma unroll
        for (int t = 0; t < 4; ++t) {
            const int idx = t * 256 + tid;
            const int ten = idx >> 9;            // 0 K, 1 V
            const int row = (idx >> 3) & 63;
            const int seg = idx & 7;
            const __half* src = (ten == 0 ? g_kh : g_vh) +
                (rowbase + j0 + row) * DMODEL + hoff + seg * 8;
            cp_async16(kvbase + stage * KVSTG_B + ten * KTILE_B + row * AT_ROWB + seg * 16, src);
        }
        cp_commit();
    };

    issueQ();
    issueKV(0, 0);
    if (ntiles > 1) issueKV(1, 1);

    float O[8][4];
    #pragma unroll
    for (int nt = 0; nt < 8; ++nt)
        #pragma unroll
        for (int i = 0; i < 4; ++i) O[nt][i] = 0.f;
    float m0 = -1e30f, m1 = -1e30f, l0 = 0.f, l1 = 0.f;

    uint32_t qh[4][4];
    const int qg0 = q0 + w * 16 + (lane >> 2);

    for (int jt = 0; jt < ntiles; ++jt) {
        if (jt + 1 < ntiles)
            asm volatile("cp.async.wait_group 1;" ::: "memory");
        else
            asm volatile("cp.async.wait_group 0;" ::: "memory");
        __syncthreads();

        if (jt == 0) {
            const int arow = w * 16 + (lane & 15);
            #pragma unroll
            for (int ks = 0; ks < 4; ++ks) {
                const uint32_t off = (uint32_t)arow * AT_ROWB + ks * 32 + ((lane >> 4) << 4);
                ldsm4(qh[ks], sbase + off);
            }
        }

        const int j0 = jt * 64;
        const bool active = (j0 <= q0 + w * 16 + 15);
        if (active) {
            const uint32_t kb = kvbase + (jt & 1) * KVSTG_B;
            const bool need_mask = (j0 + 63 > q0 + w * 16);

            // ---- S = Q K^T (already in log2 domain: Q pre-scaled)
            float S[8][4];
            #pragma unroll
            for (int nt = 0; nt < 8; ++nt)
                #pragma unroll
                for (int i = 0; i < 4; ++i) S[nt][i] = 0.f;

            #pragma unroll
            for (int ks = 0; ks < 4; ++ks) {
                const int brow = ((lane >> 4) & 1) * 8 + (lane & 7);
                const int bcolb = ks * 32 + ((lane >> 3) & 1) * 16;
                #pragma unroll
                for (int p = 0; p < 4; ++p) {
                    const uint32_t off = (uint32_t)(p * 16 + brow) * AT_ROWB + bcolb;
                    uint32_t kh[4];
                    ldsm4(kh, kb + off);
                    mma16816(S[2 * p],     qh[ks], kh[0], kh[1]);
                    mma16816(S[2 * p + 1], qh[ks], kh[2], kh[3]);
                }
            }

            // ---- masking (diag tiles only) + row max
            float mx0 = -1e30f, mx1 = -1e30f;
            if (need_mask) {
                #pragma unroll
                for (int nt = 0; nt < 8; ++nt) {
                    const int kgb = j0 + nt * 8 + (lane & 3) * 2;
                    #pragma unroll
                    for (int c = 0; c < 4; ++c) {
                        const int kg = kgb + (c & 1);
                        const int qg = qg0 + (c >> 1) * 8;
                        if (kg > qg) S[nt][c] = -1e30f;
                    }
                    mx0 = fmaxf(mx0, fmaxf(S[nt][0], S[nt][1]));
                    mx1 = fmaxf(mx1, fmaxf(S[nt][2], S[nt][3]));
                }
            } else {
                #pragma unroll
                for (int nt = 0; nt < 8; ++nt) {
                    mx0 = fmaxf(mx0, fmaxf(S[nt][0], S[nt][1]));
                    mx1 = fmaxf(mx1, fmaxf(S[nt][2], S[nt][3]));
                }
            }
            mx0 = fmaxf(mx0, __shfl_xor_sync(0xffffffffu, mx0, 1));
            mx0 = fmaxf(mx0, __shfl_xor_sync(0xffffffffu, mx0, 2));
            mx1 = fmaxf(mx1, __shfl_xor_sync(0xffffffffu, mx1, 1));
            mx1 = fmaxf(mx1, __shfl_xor_sync(0xffffffffu, mx1, 2));
            const float mn0 = fmaxf(m0, mx0);
            const float mn1 = fmaxf(m1, mx1);
            const float c0 = ex2(m0 - mn0);
            const float c1 = ex2(m1 - mn1);

            // ---- p = 2^(S - mn), row sums
            float rs0 = 0.f, rs1 = 0.f;
            #pragma unroll
            for (int nt = 0; nt < 8; ++nt) {
                float p0 = ex2(S[nt][0] - mn0);
                float p1 = ex2(S[nt][1] - mn0);
                float p2 = ex2(S[nt][2] - mn1);
                float p3 = ex2(S[nt][3] - mn1);
                S[nt][0] = p0; S[nt][1] = p1; S[nt][2] = p2; S[nt][3] = p3;
                rs0 += p0 + p1;
                rs1 += p2 + p3;
            }
            rs0 += __shfl_xor_sync(0xffffffffu, rs0, 1);
            rs0 += __shfl_xor_sync(0xffffffffu, rs0, 2);
            rs1 += __shfl_xor_sync(0xffffffffu, rs1, 1);
            rs1 += __shfl_xor_sync(0xffffffffu, rs1, 2);
            l0 = l0 * c0 + rs0;
            l1 = l1 * c1 + rs1;
            #pragma unroll
            for (int nt = 0; nt < 8; ++nt) {
                O[nt][0] *= c0; O[nt][1] *= c0;
                O[nt][2] *= c1; O[nt][3] *= c1;
            }
            m0 = mn0; m1 = mn1;

            // ---- O += P V
            #pragma unroll
            for (int ks = 0; ks < 4; ++ks) {
                uint32_t aP[4];
                aP[0] = pack_h(S[2 * ks][0],     S[2 * ks][1]);
                aP[1] = pack_h(S[2 * ks][2],     S[2 * ks][3]);
                aP[2] = pack_h(S[2 * ks + 1][0], S[2 * ks + 1][1]);
                aP[3] = pack_h(S[2 * ks + 1][2], S[2 * ks + 1][3]);
                const int mI = lane >> 3;
                const int r = lane & 7;
                #pragma unroll
                for (int p = 0; p < 4; ++p) {
                    const uint32_t off = (uint32_t)(ks * 16 + (mI & 1) * 8 + r) * AT_ROWB
                                       + p * 32 + (mI >> 1) * 16;
                    uint32_t vh[4];
                    ldsm4t(vh, kb + KTILE_B + off);
                    mma16816(O[2 * p],     aP, vh[0], vh[1]);
                    mma16816(O[2 * p + 1], aP, vh[2], vh[3]);
                }
            }
        }
        __syncthreads();
        if (jt + 2 < ntiles) issueKV(jt + 2, jt & 1);
    }

    const float inv0 = 1.f / l0;
    const float inv1 = 1.f / l1;
    const size_t r0 = rowbase + q0 + w * 16 + (lane >> 2);
    #pragma unroll
    for (int nt = 0; nt < 8; ++nt) {
        const int col = (int)hoff + nt * 8 + (lane & 3) * 2;
        *(uint32_t*)&g_ch[r0 * DMODEL + col] = pack_h(O[nt][0] * inv0, O[nt][1] * inv0);
        *(uint32_t*)&g_ch[(r0 + 8) * DMODEL + col] = pack_h(O[nt][2] * inv1, O[nt][3] * inv1);
    }
}

// ---------------------------------------------------------------------------
// Launch
// ---------------------------------------------------------------------------
extern "C" void kernel_launch(void* const* d_in, const int* in_sizes, int n_in,
                              void* d_out, int out_size)
{
    const float* x  = (const float*)d_in[0];
    const float* Wq = (const float*)d_in[1];
    const float* Wk = (const float*)d_in[2];
    const float* Wv = (const float*)d_in[3];
    const float* Wo = (const float*)d_in[4];
    const float* bo = (const float*)d_in[5];
    float* out = (float*)d_out;

    __half *xh, *wtqkv, *wto, *ch;
    cudaGetSymbolAddress((void**)&xh, g_xh);
    cudaGetSymbolAddress((void**)&wtqkv, g_wtqkv);
    cudaGetSymbolAddress((void**)&wto, g_wto);
    cudaGetSymbolAddress((void**)&ch, g_ch);

    cudaFuncSetAttribute(gemm_mma_kernel,
                         cudaFuncAttributeMaxDynamicSharedMemorySize, GEMM_SMEM);
    cudaFuncSetAttribute(attn_tc_kernel,
                         cudaFuncAttributeMaxDynamicSharedMemorySize, ATTN_SMEM);

    const int n4 = MROWS * DMODEL / 4;
    convert_kernel<<<(n4 + 255) / 256, 256>>>(x, n4);

    dim3 ts_grid(DMODEL / 32, DMODEL / 32, 4);
    tsplit4_kernel<<<ts_grid, dim3(32, 8)>>>(Wq, Wk, Wv, Wo);

    // fused QKV projection (Q pre-scaled by QSCALE in epilogue)
    dim3 gq(3 * DMODEL / 128, MROWS / 128);   // (24, 64)
    gemm_mma_kernel<<<gq, 256, GEMM_SMEM>>>(xh, wtqkv, nullptr, nullptr, 1);

    // causal flash attention
    dim3 attn_grid(SEQ / 128, BATCH * NHEAD);
    attn_tc_kernel<<<attn_grid, 256, ATTN_SMEM>>>();

    // output projection + bias
    dim3 go(DMODEL / 128, MROWS / 128);       // (8, 64)
    gemm_mma_kernel<<<go, 256, GEMM_SMEM>>>(ch, wto, out, bo, 0);
}